// round 2
// baseline (speedup 1.0000x reference)
#include <cuda_runtime.h>
#include <math.h>
#include <stdint.h>

#define B_  128
#define S_  512
#define I_  512
#define H_  1024
#define O_  512

// Scratch (device globals: allocation-free per harness rules)
__device__ __align__(256) float g_xproj[(size_t)S_ * B_ * H_];   // [s][b][h], 268 MB
__device__ __align__(256) float g_h[2][B_ * H_];                 // ping-pong hidden state

// ---------------------------------------------------------------------------
// helpers
// ---------------------------------------------------------------------------
__device__ __forceinline__ void cp_async16(void* s, const void* g) {
    uint32_t sa = (uint32_t)__cvta_generic_to_shared(s);
    asm volatile("cp.async.cg.shared.global [%0], [%1], 16;" :: "r"(sa), "l"(g));
}
__device__ __forceinline__ void cp_commit() { asm volatile("cp.async.commit_group;"); }
template <int N> __device__ __forceinline__ void cp_wait() {
    asm volatile("cp.async.wait_group %0;" :: "n"(N));
}

__device__ __forceinline__ void fma4(float4& acc, const float4 a, const float4 b) {
    acc.x = fmaf(a.x, b.x, acc.x);
    acc.y = fmaf(a.y, b.y, acc.y);
    acc.z = fmaf(a.z, b.z, acc.z);
    acc.w = fmaf(a.w, b.w, acc.w);
}

// ---------------------------------------------------------------------------
// zero initial hidden state
// ---------------------------------------------------------------------------
__global__ void k_zero_h() {
    int i = blockIdx.x * blockDim.x + threadIdx.x;
    g_h[0][i] = 0.0f;
}

// ---------------------------------------------------------------------------
// xproj[s][b][h] = sum_i x[b][s][i] * Wx[h][i] + bx[h]
// GEMM: M = B*S (row m = b*S + s), N = H, K = I
// Tile 128x64x16, 256 threads, 8x4 per thread.
// ---------------------------------------------------------------------------
#define XBM 128
#define XBN 64
#define XBK 16

__global__ __launch_bounds__(256) void k_xproj(const float* __restrict__ x,
                                               const float* __restrict__ Wx,
                                               const float* __restrict__ bx) {
    __shared__ float As[XBK][XBM + 4];
    __shared__ float Bs[XBK][XBN + 4];
    const int tid = threadIdx.x;
    const int m0 = blockIdx.y * XBM;
    const int n0 = blockIdx.x * XBN;
    const int tx = tid & 15;        // 16 col-groups of 4
    const int ty = tid >> 4;        // 16 row-groups of 8

    float acc[8][4];
#pragma unroll
    for (int i = 0; i < 8; i++)
#pragma unroll
        for (int j = 0; j < 4; j++) acc[i][j] = 0.0f;

    const int lr = tid >> 2;          // 0..63
    const int lc = (tid & 3) << 2;    // 0,4,8,12

    for (int k0 = 0; k0 < I_; k0 += XBK) {
        // A tile: 128 rows x 16 k (2 float4 per thread), store transposed
#pragma unroll
        for (int rr = 0; rr < 2; rr++) {
            int r = lr + rr * 64;
            float4 v = *(const float4*)(x + (size_t)(m0 + r) * I_ + k0 + lc);
            As[lc + 0][r] = v.x; As[lc + 1][r] = v.y;
            As[lc + 2][r] = v.z; As[lc + 3][r] = v.w;
        }
        // B tile: 64 rows x 16 k (1 float4 per thread), store transposed
        {
            float4 v = *(const float4*)(Wx + (size_t)(n0 + lr) * I_ + k0 + lc);
            Bs[lc + 0][lr] = v.x; Bs[lc + 1][lr] = v.y;
            Bs[lc + 2][lr] = v.z; Bs[lc + 3][lr] = v.w;
        }
        __syncthreads();
#pragma unroll
        for (int k = 0; k < XBK; k++) {
            float a[8], b[4];
#pragma unroll
            for (int i = 0; i < 8; i++) a[i] = As[k][ty * 8 + i];
#pragma unroll
            for (int j = 0; j < 4; j++) b[j] = Bs[k][tx * 4 + j];
#pragma unroll
            for (int i = 0; i < 8; i++)
#pragma unroll
                for (int j = 0; j < 4; j++) acc[i][j] = fmaf(a[i], b[j], acc[i][j]);
        }
        __syncthreads();
    }

    // epilogue: scatter to [s][b][h] layout, add bias
    const int h0 = n0 + tx * 4;
    float4 bias = *(const float4*)(bx + h0);
#pragma unroll
    for (int i = 0; i < 8; i++) {
        int m = m0 + ty * 8 + i;
        int b = m / S_;
        int s = m % S_;
        float4 v;
        v.x = acc[i][0] + bias.x;
        v.y = acc[i][1] + bias.y;
        v.z = acc[i][2] + bias.z;
        v.w = acc[i][3] + bias.w;
        *(float4*)(g_xproj + ((size_t)s * B_ + b) * H_ + h0) = v;
    }
}

// ---------------------------------------------------------------------------
// One recurrence step: h_out[b][j] = tanh( xproj[t][b][j] + sum_k h_in[b][k]*Wh[j][k] )
// 128 CTAs (32 j-tiles x 4 b-tiles), 256 threads, tile 32x32, 2x2 per thread,
// float4 dot-products along k, cp.async double-buffered K-chunks of 64.
// ---------------------------------------------------------------------------
#define KC   64
#define SROW (KC + 4)   // 68 floats: 16B-aligned rows, 2-way max conflicts

__global__ __launch_bounds__(256) void k_step(const float* __restrict__ Wh,
                                              int t, int cur) {
    __shared__ float hs[2][32][SROW];
    __shared__ float ws[2][32][SROW];
    const int tid = threadIdx.x;
    const int jb = blockIdx.x * 32;
    const int bb = blockIdx.y * 32;
    const float* __restrict__ hin = g_h[cur];
    float* __restrict__ hout = g_h[cur ^ 1];

    const int r0 = tid >> 4;          // 0..15 (load rows, +16 for q=1)
    const int c0 = (tid & 15) << 2;   // float col 0..60

    float4 acc00 = {0,0,0,0}, acc01 = {0,0,0,0}, acc10 = {0,0,0,0}, acc11 = {0,0,0,0};
    const int b0 = (tid >> 4) << 1;   // 0..30, step 2
    const int j0 = tid & 15;          // cols j0 and j0+16

    // prologue: chunk 0
    {
#pragma unroll
        for (int q = 0; q < 2; q++) {
            int row = r0 + q * 16;
            cp_async16(&hs[0][row][c0], hin + (size_t)(bb + row) * H_ + c0);
            cp_async16(&ws[0][row][c0], Wh  + (size_t)(jb + row) * H_ + c0);
        }
        cp_commit();
    }

    for (int c = 0; c < H_ / KC; c++) {
        if (c + 1 < H_ / KC) {
            int k0 = (c + 1) * KC;
            int nb = (c + 1) & 1;
#pragma unroll
            for (int q = 0; q < 2; q++) {
                int row = r0 + q * 16;
                cp_async16(&hs[nb][row][c0], hin + (size_t)(bb + row) * H_ + k0 + c0);
                cp_async16(&ws[nb][row][c0], Wh  + (size_t)(jb + row) * H_ + k0 + c0);
            }
            cp_commit();
            cp_wait<1>();
        } else {
            cp_wait<0>();
        }
        __syncthreads();
        const int buf = c & 1;
#pragma unroll
        for (int k4 = 0; k4 < KC; k4 += 4) {
            float4 a0 = *(const float4*)&hs[buf][b0    ][k4];
            float4 a1 = *(const float4*)&hs[buf][b0 + 1][k4];
            float4 w0 = *(const float4*)&ws[buf][j0     ][k4];
            float4 w1 = *(const float4*)&ws[buf][j0 + 16][k4];
            fma4(acc00, a0, w0); fma4(acc01, a0, w1);
            fma4(acc10, a1, w0); fma4(acc11, a1, w1);
        }
        __syncthreads();
    }

    const size_t xbase = (size_t)t * B_ * H_;
    {
        int bg = bb + b0, jg = jb + j0;
        float z;
        z = (acc00.x + acc00.y) + (acc00.z + acc00.w);
        z += g_xproj[xbase + (size_t)bg * H_ + jg];
        hout[(size_t)bg * H_ + jg] = tanhf(z);

        z = (acc01.x + acc01.y) + (acc01.z + acc01.w);
        z += g_xproj[xbase + (size_t)bg * H_ + jg + 16];
        hout[(size_t)bg * H_ + jg + 16] = tanhf(z);

        z = (acc10.x + acc10.y) + (acc10.z + acc10.w);
        z += g_xproj[xbase + (size_t)(bg + 1) * H_ + jg];
        hout[(size_t)(bg + 1) * H_ + jg] = tanhf(z);

        z = (acc11.x + acc11.y) + (acc11.z + acc11.w);
        z += g_xproj[xbase + (size_t)(bg + 1) * H_ + jg + 16];
        hout[(size_t)(bg + 1) * H_ + jg + 16] = tanhf(z);
    }
}

// ---------------------------------------------------------------------------
// Final projection: out[b][o] = sum_k h[b][k] * Wp[o][k] + bp[o]
// Same structure as k_step (32x32 tiles, K=1024), reads g_h[0].
// ---------------------------------------------------------------------------
__global__ __launch_bounds__(256) void k_final(const float* __restrict__ Wp,
                                               const float* __restrict__ bp,
                                               float* __restrict__ out) {
    __shared__ float hs[2][32][SROW];
    __shared__ float ws[2][32][SROW];
    const int tid = threadIdx.x;
    const int jb = blockIdx.x * 32;
    const int bb = blockIdx.y * 32;
    const float* __restrict__ hin = g_h[0];

    const int r0 = tid >> 4;
    const int c0 = (tid & 15) << 2;

    float4 acc00 = {0,0,0,0}, acc01 = {0,0,0,0}, acc10 = {0,0,0,0}, acc11 = {0,0,0,0};
    const int b0 = (tid >> 4) << 1;
    const int j0 = tid & 15;

    {
#pragma unroll
        for (int q = 0; q < 2; q++) {
            int row = r0 + q * 16;
            cp_async16(&hs[0][row][c0], hin + (size_t)(bb + row) * H_ + c0);
            cp_async16(&ws[0][row][c0], Wp  + (size_t)(jb + row) * H_ + c0);
        }
        cp_commit();
    }

    for (int c = 0; c < H_ / KC; c++) {
        if (c + 1 < H_ / KC) {
            int k0 = (c + 1) * KC;
            int nb = (c + 1) & 1;
#pragma unroll
            for (int q = 0; q < 2; q++) {
                int row = r0 + q * 16;
                cp_async16(&hs[nb][row][c0], hin + (size_t)(bb + row) * H_ + k0 + c0);
                cp_async16(&ws[nb][row][c0], Wp  + (size_t)(jb + row) * H_ + k0 + c0);
            }
            cp_commit();
            cp_wait<1>();
        } else {
            cp_wait<0>();
        }
        __syncthreads();
        const int buf = c & 1;
#pragma unroll
        for (int k4 = 0; k4 < KC; k4 += 4) {
            float4 a0 = *(const float4*)&hs[buf][b0    ][k4];
            float4 a1 = *(const float4*)&hs[buf][b0 + 1][k4];
            float4 w0 = *(const float4*)&ws[buf][j0     ][k4];
            float4 w1 = *(const float4*)&ws[buf][j0 + 16][k4];
            fma4(acc00, a0, w0); fma4(acc01, a0, w1);
            fma4(acc10, a1, w0); fma4(acc11, a1, w1);
        }
        __syncthreads();
    }

    {
        int bg = bb + b0, jg = jb + j0;
        float z;
        z = (acc00.x + acc00.y) + (acc00.z + acc00.w) + bp[jg];
        out[(size_t)bg * O_ + jg] = z;
        z = (acc01.x + acc01.y) + (acc01.z + acc01.w) + bp[jg + 16];
        out[(size_t)bg * O_ + jg + 16] = z;
        z = (acc10.x + acc10.y) + (acc10.z + acc10.w) + bp[jg];
        out[(size_t)(bg + 1) * O_ + jg] = z;
        z = (acc11.x + acc11.y) + (acc11.z + acc11.w) + bp[jg + 16];
        out[(size_t)(bg + 1) * O_ + jg + 16] = z;
    }
}

// ---------------------------------------------------------------------------
// launch
// ---------------------------------------------------------------------------
extern "C" void kernel_launch(void* const* d_in, const int* in_sizes, int n_in,
                              void* d_out, int out_size) {
    const float* x  = (const float*)d_in[0];
    const float* Wx = (const float*)d_in[1];
    const float* bx = (const float*)d_in[2];
    const float* Wh = (const float*)d_in[3];
    const float* Wp = (const float*)d_in[4];
    const float* bp = (const float*)d_in[5];
    float* out = (float*)d_out;

    k_zero_h<<<(B_ * H_) / 256, 256>>>();
    k_xproj<<<dim3(H_ / XBN, (B_ * S_) / XBM), 256>>>(x, Wx, bx);
    for (int t = 0; t < S_; t++) {
        k_step<<<dim3(H_ / 32, B_ / 32), 256>>>(Wh, t, t & 1);
    }
    k_final<<<dim3(O_ / 32, B_ / 32), 256>>>(Wp, bp, out);
}

// round 3
// speedup vs baseline: 1.8063x; 1.8063x over previous
#include <cuda_runtime.h>
#include <cuda_bf16.h>
#include <math.h>
#include <stdint.h>

#define B_  128
#define S_  512
#define I_  512
#define H_  1024
#define O_  512

// Scratch (device globals: allocation-free per harness rules)
__device__ __align__(256) float g_xproj[(size_t)S_ * B_ * H_];        // [s][b][h]
__device__ __align__(256) float g_hf[B_ * H_];                        // fp32 h (for k_final)
__device__ __align__(256) __nv_bfloat16 g_hbf[2][2][B_ * H_];         // [pingpong][hi/lo][b][k]
__device__ __align__(256) __nv_bfloat16 g_Whbf[2][(size_t)H_ * H_];   // [hi/lo][j][k]

// ---------------------------------------------------------------------------
// helpers
// ---------------------------------------------------------------------------
__device__ __forceinline__ void cp_async16(void* s, const void* g) {
    uint32_t sa = (uint32_t)__cvta_generic_to_shared(s);
    asm volatile("cp.async.cg.shared.global [%0], [%1], 16;" :: "r"(sa), "l"(g));
}
__device__ __forceinline__ void cp_commit() { asm volatile("cp.async.commit_group;"); }
template <int N> __device__ __forceinline__ void cp_wait() {
    asm volatile("cp.async.wait_group %0;" :: "n"(N));
}
__device__ __forceinline__ uint32_t sptr(const void* p) {
    return (uint32_t)__cvta_generic_to_shared(p);
}
__device__ __forceinline__ void ldmatrix_x4(uint32_t& r0, uint32_t& r1, uint32_t& r2, uint32_t& r3,
                                            uint32_t addr) {
    asm volatile("ldmatrix.sync.aligned.m8n8.x4.shared.b16 {%0,%1,%2,%3}, [%4];"
                 : "=r"(r0), "=r"(r1), "=r"(r2), "=r"(r3) : "r"(addr));
}
__device__ __forceinline__ void ldmatrix_x2(uint32_t& r0, uint32_t& r1, uint32_t addr) {
    asm volatile("ldmatrix.sync.aligned.m8n8.x2.shared.b16 {%0,%1}, [%2];"
                 : "=r"(r0), "=r"(r1) : "r"(addr));
}
__device__ __forceinline__ void mma_bf16(float& c0, float& c1, float& c2, float& c3,
                                         uint32_t a0, uint32_t a1, uint32_t a2, uint32_t a3,
                                         uint32_t b0, uint32_t b1) {
    asm volatile("mma.sync.aligned.m16n8k16.row.col.f32.bf16.bf16.f32 "
                 "{%0,%1,%2,%3}, {%4,%5,%6,%7}, {%8,%9}, {%0,%1,%2,%3};"
                 : "+f"(c0), "+f"(c1), "+f"(c2), "+f"(c3)
                 : "r"(a0), "r"(a1), "r"(a2), "r"(a3), "r"(b0), "r"(b1));
}
__device__ __forceinline__ void fma4(float4& acc, const float4 a, const float4 b) {
    acc.x = fmaf(a.x, b.x, acc.x);
    acc.y = fmaf(a.y, b.y, acc.y);
    acc.z = fmaf(a.z, b.z, acc.z);
    acc.w = fmaf(a.w, b.w, acc.w);
}

// ---------------------------------------------------------------------------
// init kernels
// ---------------------------------------------------------------------------
__global__ void k_zero_h() {
    int i = blockIdx.x * blockDim.x + threadIdx.x;   // 2*B*H halves (hi+lo of buffer 0)
    ((__nv_bfloat16*)g_hbf[0])[i] = __float2bfloat16(0.0f);
}

__global__ void k_convert_wh(const float* __restrict__ Wh) {
    int i = blockIdx.x * blockDim.x + threadIdx.x;   // H*H
    float v = Wh[i];
    __nv_bfloat16 hi = __float2bfloat16(v);
    float lo = v - __bfloat162float(hi);
    g_Whbf[0][i] = hi;
    g_Whbf[1][i] = __float2bfloat16(lo);
}

// ---------------------------------------------------------------------------
// xproj[s][b][h] = sum_i x[b][s][i] * Wx[h][i] + bx[h]  (fp32 SIMT)
// ---------------------------------------------------------------------------
#define XBM 128
#define XBN 64
#define XBK 16

__global__ __launch_bounds__(256) void k_xproj(const float* __restrict__ x,
                                               const float* __restrict__ Wx,
                                               const float* __restrict__ bx) {
    __shared__ float As[XBK][XBM + 4];
    __shared__ float Bs[XBK][XBN + 4];
    const int tid = threadIdx.x;
    const int m0 = blockIdx.y * XBM;
    const int n0 = blockIdx.x * XBN;
    const int tx = tid & 15;
    const int ty = tid >> 4;

    float acc[8][4];
#pragma unroll
    for (int i = 0; i < 8; i++)
#pragma unroll
        for (int j = 0; j < 4; j++) acc[i][j] = 0.0f;

    const int lr = tid >> 2;
    const int lc = (tid & 3) << 2;

    for (int k0 = 0; k0 < I_; k0 += XBK) {
#pragma unroll
        for (int rr = 0; rr < 2; rr++) {
            int r = lr + rr * 64;
            float4 v = *(const float4*)(x + (size_t)(m0 + r) * I_ + k0 + lc);
            As[lc + 0][r] = v.x; As[lc + 1][r] = v.y;
            As[lc + 2][r] = v.z; As[lc + 3][r] = v.w;
        }
        {
            float4 v = *(const float4*)(Wx + (size_t)(n0 + lr) * I_ + k0 + lc);
            Bs[lc + 0][lr] = v.x; Bs[lc + 1][lr] = v.y;
            Bs[lc + 2][lr] = v.z; Bs[lc + 3][lr] = v.w;
        }
        __syncthreads();
#pragma unroll
        for (int k = 0; k < XBK; k++) {
            float a[8], b[4];
#pragma unroll
            for (int i = 0; i < 8; i++) a[i] = As[k][ty * 8 + i];
#pragma unroll
            for (int j = 0; j < 4; j++) b[j] = Bs[k][tx * 4 + j];
#pragma unroll
            for (int i = 0; i < 8; i++)
#pragma unroll
                for (int j = 0; j < 4; j++) acc[i][j] = fmaf(a[i], b[j], acc[i][j]);
        }
        __syncthreads();
    }

    const int h0 = n0 + tx * 4;
    float4 bias = *(const float4*)(bx + h0);
#pragma unroll
    for (int i = 0; i < 8; i++) {
        int m = m0 + ty * 8 + i;
        int b = m / S_;
        int s = m % S_;
        float4 v;
        v.x = acc[i][0] + bias.x;
        v.y = acc[i][1] + bias.y;
        v.z = acc[i][2] + bias.z;
        v.w = acc[i][3] + bias.w;
        *(float4*)(g_xproj + ((size_t)s * B_ + b) * H_ + h0) = v;
    }
}

// ---------------------------------------------------------------------------
// Recurrence step via bf16 mma.sync with 2-term operand split.
// Grid (32 j-tiles, 4 b-tiles), CTA tile 32b x 32j, 8 warps, warp = m16n8 frag.
// ---------------------------------------------------------------------------
#define KC    64
#define PITCH 72   // halves per SMEM row (64 data + 8 pad) -> 144B pitch, ldmatrix conflict-free

__global__ __launch_bounds__(256) void k_step_mma(int t, int cur) {
    __shared__ __nv_bfloat16 sh[2][2][32 * PITCH];  // [buf][hi/lo] h tile (rows = b)
    __shared__ __nv_bfloat16 sw[2][2][32 * PITCH];  // [buf][hi/lo] Wh tile (rows = j)

    const int tid = threadIdx.x;
    const int jb = blockIdx.x * 32;
    const int bb = blockIdx.y * 32;

    const __nv_bfloat16* __restrict__ hin_hi = g_hbf[cur][0];
    const __nv_bfloat16* __restrict__ hin_lo = g_hbf[cur][1];
    __nv_bfloat16* __restrict__ hout_hi = g_hbf[cur ^ 1][0];
    __nv_bfloat16* __restrict__ hout_lo = g_hbf[cur ^ 1][1];
    const __nv_bfloat16* __restrict__ wh_hi = g_Whbf[0];
    const __nv_bfloat16* __restrict__ wh_lo = g_Whbf[1];

    const int lrow = tid >> 3;          // 0..31
    const int lc8  = (tid & 7) * 8;     // half-offset, 16B each

    // prologue: chunk 0
    {
        cp_async16(&sh[0][0][lrow * PITCH + lc8], hin_hi + (size_t)(bb + lrow) * H_ + lc8);
        cp_async16(&sh[0][1][lrow * PITCH + lc8], hin_lo + (size_t)(bb + lrow) * H_ + lc8);
        cp_async16(&sw[0][0][lrow * PITCH + lc8], wh_hi + (size_t)(jb + lrow) * H_ + lc8);
        cp_async16(&sw[0][1][lrow * PITCH + lc8], wh_lo + (size_t)(jb + lrow) * H_ + lc8);
        cp_commit();
    }

    const int wid = tid >> 5;
    const int lane = tid & 31;
    const int wm = (wid & 1) * 16;      // warp m offset in 32-row tile
    const int wn = (wid >> 1) * 8;      // warp n offset in 32-col tile

    // ldmatrix lane addressing (element offsets within a tile)
    const int a_row  = wm + (lane & 7) + ((lane >> 3) & 1) * 8;
    const int a_koff = (lane >> 4) * 8;
    const int b_l    = lane & 15;
    const int b_row  = wn + (b_l & 7);
    const int b_koff = ((b_l >> 3) & 1) * 8;

    float c0 = 0.f, c1 = 0.f, c2 = 0.f, c3 = 0.f;

    for (int c = 0; c < H_ / KC; c++) {
        if (c + 1 < H_ / KC) {
            int k0 = (c + 1) * KC;
            int nb = (c + 1) & 1;
            cp_async16(&sh[nb][0][lrow * PITCH + lc8], hin_hi + (size_t)(bb + lrow) * H_ + k0 + lc8);
            cp_async16(&sh[nb][1][lrow * PITCH + lc8], hin_lo + (size_t)(bb + lrow) * H_ + k0 + lc8);
            cp_async16(&sw[nb][0][lrow * PITCH + lc8], wh_hi + (size_t)(jb + lrow) * H_ + k0 + lc8);
            cp_async16(&sw[nb][1][lrow * PITCH + lc8], wh_lo + (size_t)(jb + lrow) * H_ + k0 + lc8);
            cp_commit();
            cp_wait<1>();
        } else {
            cp_wait<0>();
        }
        __syncthreads();
        const int buf = c & 1;
#pragma unroll
        for (int kk = 0; kk < KC; kk += 16) {
            uint32_t ah0, ah1, ah2, ah3, al0, al1, al2, al3;
            uint32_t bh0, bh1, bl0, bl1;
            ldmatrix_x4(ah0, ah1, ah2, ah3, sptr(&sh[buf][0][a_row * PITCH + kk + a_koff]));
            ldmatrix_x4(al0, al1, al2, al3, sptr(&sh[buf][1][a_row * PITCH + kk + a_koff]));
            ldmatrix_x2(bh0, bh1, sptr(&sw[buf][0][b_row * PITCH + kk + b_koff]));
            ldmatrix_x2(bl0, bl1, sptr(&sw[buf][1][b_row * PITCH + kk + b_koff]));
            mma_bf16(c0, c1, c2, c3, ah0, ah1, ah2, ah3, bh0, bh1);  // hi*hi
            mma_bf16(c0, c1, c2, c3, ah0, ah1, ah2, ah3, bl0, bl1);  // hi*lo
            mma_bf16(c0, c1, c2, c3, al0, al1, al2, al3, bh0, bh1);  // lo*hi
        }
        __syncthreads();
    }

    // epilogue: z += xproj, h = tanh(z); write fp32 + bf16 hi/lo
    const float* __restrict__ xp = g_xproj + (size_t)t * B_ * H_;
    const int r  = lane >> 2;            // 0..7
    const int cc = (lane & 3) * 2;
    const int jg = jb + wn + cc;

    {
        int bg = bb + wm + r;
        float2 xv = *(const float2*)(xp + (size_t)bg * H_ + jg);
        float v0 = tanhf(c0 + xv.x);
        float v1 = tanhf(c1 + xv.y);
        *(float2*)(g_hf + (size_t)bg * H_ + jg) = make_float2(v0, v1);
        __nv_bfloat16 h0 = __float2bfloat16(v0);
        __nv_bfloat16 h1 = __float2bfloat16(v1);
        __nv_bfloat162 hv; hv.x = h0; hv.y = h1;
        __nv_bfloat162 lv;
        lv.x = __float2bfloat16(v0 - __bfloat162float(h0));
        lv.y = __float2bfloat16(v1 - __bfloat162float(h1));
        *(__nv_bfloat162*)(hout_hi + (size_t)bg * H_ + jg) = hv;
        *(__nv_bfloat162*)(hout_lo + (size_t)bg * H_ + jg) = lv;
    }
    {
        int bg = bb + wm + r + 8;
        float2 xv = *(const float2*)(xp + (size_t)bg * H_ + jg);
        float v0 = tanhf(c2 + xv.x);
        float v1 = tanhf(c3 + xv.y);
        *(float2*)(g_hf + (size_t)bg * H_ + jg) = make_float2(v0, v1);
        __nv_bfloat16 h0 = __float2bfloat16(v0);
        __nv_bfloat16 h1 = __float2bfloat16(v1);
        __nv_bfloat162 hv; hv.x = h0; hv.y = h1;
        __nv_bfloat162 lv;
        lv.x = __float2bfloat16(v0 - __bfloat162float(h0));
        lv.y = __float2bfloat16(v1 - __bfloat162float(h1));
        *(__nv_bfloat162*)(hout_hi + (size_t)bg * H_ + jg) = hv;
        *(__nv_bfloat162*)(hout_lo + (size_t)bg * H_ + jg) = lv;
    }
}

// ---------------------------------------------------------------------------
// Final projection: out[b][o] = sum_k h[b][k] * Wp[o][k] + bp[o]  (fp32 SIMT)
// ---------------------------------------------------------------------------
#define SROW (KC + 4)

__global__ __launch_bounds__(256) void k_final(const float* __restrict__ Wp,
                                               const float* __restrict__ bp,
                                               float* __restrict__ out) {
    __shared__ float hs[2][32][SROW];
    __shared__ float ws[2][32][SROW];
    const int tid = threadIdx.x;
    const int jb = blockIdx.x * 32;
    const int bb = blockIdx.y * 32;
    const float* __restrict__ hin = g_hf;

    const int r0 = tid >> 4;
    const int c0 = (tid & 15) << 2;

    float4 acc00 = {0,0,0,0}, acc01 = {0,0,0,0}, acc10 = {0,0,0,0}, acc11 = {0,0,0,0};
    const int b0 = (tid >> 4) << 1;
    const int j0 = tid & 15;

    {
#pragma unroll
        for (int q = 0; q < 2; q++) {
            int row = r0 + q * 16;
            cp_async16(&hs[0][row][c0], hin + (size_t)(bb + row) * H_ + c0);
            cp_async16(&ws[0][row][c0], Wp  + (size_t)(jb + row) * H_ + c0);
        }
        cp_commit();
    }

    for (int c = 0; c < H_ / KC; c++) {
        if (c + 1 < H_ / KC) {
            int k0 = (c + 1) * KC;
            int nb = (c + 1) & 1;
#pragma unroll
            for (int q = 0; q < 2; q++) {
                int row = r0 + q * 16;
                cp_async16(&hs[nb][row][c0], hin + (size_t)(bb + row) * H_ + k0 + c0);
                cp_async16(&ws[nb][row][c0], Wp  + (size_t)(jb + row) * H_ + k0 + c0);
            }
            cp_commit();
            cp_wait<1>();
        } else {
            cp_wait<0>();
        }
        __syncthreads();
        const int buf = c & 1;
#pragma unroll
        for (int k4 = 0; k4 < KC; k4 += 4) {
            float4 a0 = *(const float4*)&hs[buf][b0    ][k4];
            float4 a1 = *(const float4*)&hs[buf][b0 + 1][k4];
            float4 w0 = *(const float4*)&ws[buf][j0     ][k4];
            float4 w1 = *(const float4*)&ws[buf][j0 + 16][k4];
            fma4(acc00, a0, w0); fma4(acc01, a0, w1);
            fma4(acc10, a1, w0); fma4(acc11, a1, w1);
        }
        __syncthreads();
    }

    {
        int bg = bb + b0, jg = jb + j0;
        float z;
        z = (acc00.x + acc00.y) + (acc00.z + acc00.w) + bp[jg];
        out[(size_t)bg * O_ + jg] = z;
        z = (acc01.x + acc01.y) + (acc01.z + acc01.w) + bp[jg + 16];
        out[(size_t)bg * O_ + jg + 16] = z;
        z = (acc10.x + acc10.y) + (acc10.z + acc10.w) + bp[jg];
        out[(size_t)(bg + 1) * O_ + jg] = z;
        z = (acc11.x + acc11.y) + (acc11.z + acc11.w) + bp[jg + 16];
        out[(size_t)(bg + 1) * O_ + jg + 16] = z;
    }
}

// ---------------------------------------------------------------------------
// launch
// ---------------------------------------------------------------------------
extern "C" void kernel_launch(void* const* d_in, const int* in_sizes, int n_in,
                              void* d_out, int out_size) {
    const float* x  = (const float*)d_in[0];
    const float* Wx = (const float*)d_in[1];
    const float* bx = (const float*)d_in[2];
    const float* Wh = (const float*)d_in[3];
    const float* Wp = (const float*)d_in[4];
    const float* bp = (const float*)d_in[5];
    float* out = (float*)d_out;

    k_zero_h<<<(2 * B_ * H_) / 256, 256>>>();
    k_convert_wh<<<(H_ * H_) / 256, 256>>>(Wh);
    k_xproj<<<dim3(H_ / XBN, (B_ * S_) / XBM), 256>>>(x, Wx, bx);
    for (int t = 0; t < S_; t++) {
        k_step_mma<<<dim3(H_ / 32, B_ / 32), 256>>>(t, t & 1);
    }
    k_final<<<dim3(O_ / 32, B_ / 32), 256>>>(Wp, bp, out);
}

// round 4
// speedup vs baseline: 2.3141x; 1.2811x over previous
#include <cuda_runtime.h>
#include <cuda_bf16.h>
#include <math.h>
#include <stdint.h>

#define B_   128
#define S_   512
#define I_   512
#define H_   1024
#define O_   512
#define NCTA 128

// ---------------------------------------------------------------------------
// device globals (allocation-free scratch)
// ---------------------------------------------------------------------------
__device__ __align__(256) float g_xproj[(size_t)S_ * B_ * H_];        // [m=s*B+b][h]
__device__ __align__(256) float g_hf[B_ * H_];                        // fp32 final h
__device__ __align__(256) __nv_bfloat16 g_hbf[2][2][B_ * H_];         // [pingpong][hi/lo][b][k]
__device__ __align__(256) __nv_bfloat16 g_xr[2][(size_t)S_ * B_ * I_];// [hi/lo][m=s*B+b][i]
__device__ __align__(256) __nv_bfloat16 g_Wxbf[2][(size_t)H_ * I_];   // [hi/lo][h][i]
__device__ unsigned g_barc = 0;
__device__ volatile unsigned g_barg = 0;

// ---------------------------------------------------------------------------
// helpers
// ---------------------------------------------------------------------------
__device__ __forceinline__ void cp_async16(void* s, const void* g) {
    uint32_t sa = (uint32_t)__cvta_generic_to_shared(s);
    asm volatile("cp.async.cg.shared.global [%0], [%1], 16;" :: "r"(sa), "l"(g));
}
__device__ __forceinline__ void cp_commit() { asm volatile("cp.async.commit_group;"); }
template <int N> __device__ __forceinline__ void cp_wait() {
    asm volatile("cp.async.wait_group %0;" :: "n"(N));
}
__device__ __forceinline__ uint32_t sptr(const void* p) {
    return (uint32_t)__cvta_generic_to_shared(p);
}
__device__ __forceinline__ void ldsm_x4(uint32_t& r0, uint32_t& r1, uint32_t& r2, uint32_t& r3,
                                        uint32_t addr) {
    asm volatile("ldmatrix.sync.aligned.m8n8.x4.shared.b16 {%0,%1,%2,%3}, [%4];"
                 : "=r"(r0), "=r"(r1), "=r"(r2), "=r"(r3) : "r"(addr));
}
__device__ __forceinline__ void mma_bf16(float& c0, float& c1, float& c2, float& c3,
                                         uint32_t a0, uint32_t a1, uint32_t a2, uint32_t a3,
                                         uint32_t b0, uint32_t b1) {
    asm volatile("mma.sync.aligned.m16n8k16.row.col.f32.bf16.bf16.f32 "
                 "{%0,%1,%2,%3}, {%4,%5,%6,%7}, {%8,%9}, {%0,%1,%2,%3};"
                 : "+f"(c0), "+f"(c1), "+f"(c2), "+f"(c3)
                 : "r"(a0), "r"(a1), "r"(a2), "r"(a3), "r"(b0), "r"(b1));
}
__device__ __forceinline__ void fma4(float4& acc, const float4 a, const float4 b) {
    acc.x = fmaf(a.x, b.x, acc.x);
    acc.y = fmaf(a.y, b.y, acc.y);
    acc.z = fmaf(a.z, b.z, acc.z);
    acc.w = fmaf(a.w, b.w, acc.w);
}
__device__ __forceinline__ void split2(float v, __nv_bfloat16& hi, __nv_bfloat16& lo) {
    hi = __float2bfloat16(v);
    lo = __float2bfloat16(v - __bfloat162float(hi));
}

// grid-wide barrier (all NCTA CTAs co-resident)
__device__ __forceinline__ void gridbar() {
    __syncthreads();
    if (threadIdx.x == 0) {
        __threadfence();
        unsigned gen = g_barg;
        if (atomicAdd(&g_barc, 1u) == NCTA - 1) {
            g_barc = 0;
            __threadfence();
            g_barg = gen + 1;
        } else {
            while (g_barg == gen) { }
            __threadfence();
        }
    }
    __syncthreads();
}

// ---------------------------------------------------------------------------
// conversions: x -> reordered hi/lo bf16 [m=s*B+b][i]; Wx -> hi/lo
// ---------------------------------------------------------------------------
__global__ __launch_bounds__(256) void k_convert_x(const float* __restrict__ x) {
    int gid = blockIdx.x * blockDim.x + threadIdx.x;   // S*B*I/4 units
    int i4 = (gid & (I_ / 4 - 1)) * 4;
    int m  = gid >> 7;                                 // I_/4 = 128
    int s = m / B_, b = m % B_;
    float4 v = *(const float4*)(x + ((size_t)b * S_ + s) * I_ + i4);
    __nv_bfloat16 h0, l0, h1, l1, h2, l2, h3, l3;
    split2(v.x, h0, l0); split2(v.y, h1, l1);
    split2(v.z, h2, l2); split2(v.w, h3, l3);
    __nv_bfloat162 p;
    __nv_bfloat16* dh = g_xr[0] + (size_t)m * I_ + i4;
    __nv_bfloat16* dl = g_xr[1] + (size_t)m * I_ + i4;
    p.x = h0; p.y = h1; *(__nv_bfloat162*)(dh)     = p;
    p.x = h2; p.y = h3; *(__nv_bfloat162*)(dh + 2) = p;
    p.x = l0; p.y = l1; *(__nv_bfloat162*)(dl)     = p;
    p.x = l2; p.y = l3; *(__nv_bfloat162*)(dl + 2) = p;
}

__global__ __launch_bounds__(256) void k_convert_wx(const float* __restrict__ Wx) {
    int gid = blockIdx.x * blockDim.x + threadIdx.x;   // H*I/4 units
    int i = gid * 4;
    float4 v = *(const float4*)(Wx + i);
    __nv_bfloat16 h0, l0, h1, l1, h2, l2, h3, l3;
    split2(v.x, h0, l0); split2(v.y, h1, l1);
    split2(v.z, h2, l2); split2(v.w, h3, l3);
    __nv_bfloat162 p;
    p.x = h0; p.y = h1; *(__nv_bfloat162*)(g_Wxbf[0] + i)     = p;
    p.x = h2; p.y = h3; *(__nv_bfloat162*)(g_Wxbf[0] + i + 2) = p;
    p.x = l0; p.y = l1; *(__nv_bfloat162*)(g_Wxbf[1] + i)     = p;
    p.x = l2; p.y = l3; *(__nv_bfloat162*)(g_Wxbf[1] + i + 2) = p;
}

// ---------------------------------------------------------------------------
// xproj GEMM via bf16x2-split mma: g_xproj[m][h] = sum_i xr[m][i]*Wx[h][i] + bx[h]
// CTA tile 128m x 64n, warps 4(m) x 2(n), warp tile 32x32. K chunks of 64.
// ---------------------------------------------------------------------------
#define XKC  64
#define XPA  72   // A smem pitch (halves)

__global__ __launch_bounds__(256) void k_xproj_mma(const float* __restrict__ bx) {
    extern __shared__ __nv_bfloat16 dsm[];
    // layout: A[buf][sp][128*72], then B[buf][sp][64*72]
    __nv_bfloat16* sa = dsm;
    __nv_bfloat16* sb = dsm + 2 * 2 * 128 * XPA;

    const int tid = threadIdx.x;
    const int lane = tid & 31, wid = tid >> 5;
    const int n0 = blockIdx.x * 64;
    const int m0 = blockIdx.y * 128;
    const int wm = (wid & 3) * 32;
    const int wn = (wid >> 2) * 32;

    float acc[2][4][4];
#pragma unroll
    for (int a = 0; a < 2; a++)
#pragma unroll
        for (int b = 0; b < 4; b++)
#pragma unroll
            for (int c = 0; c < 4; c++) acc[a][b][c] = 0.0f;

    // cp.async tile loaders
    auto load_chunk = [&](int buf, int k0) {
#pragma unroll
        for (int sp = 0; sp < 2; sp++) {
            __nv_bfloat16* da = sa + (size_t)(buf * 2 + sp) * 128 * XPA;
            const __nv_bfloat16* ga = g_xr[sp];
#pragma unroll
            for (int q = 0; q < 4; q++) {
                int u = tid + q * 256;          // 1024 units: 128 rows x 8
                int row = u >> 3, c16 = (u & 7) * 8;
                cp_async16(da + row * XPA + c16,
                           ga + (size_t)(m0 + row) * I_ + k0 + c16);
            }
            __nv_bfloat16* db = sb + (size_t)(buf * 2 + sp) * 64 * XPA;
            const __nv_bfloat16* gb = g_Wxbf[sp];
#pragma unroll
            for (int q = 0; q < 2; q++) {
                int u = tid + q * 256;          // 512 units: 64 rows x 8
                int row = u >> 3, c16 = (u & 7) * 8;
                cp_async16(db + row * XPA + c16,
                           gb + (size_t)(n0 + row) * I_ + k0 + c16);
            }
        }
        cp_commit();
    };

    load_chunk(0, 0);

    // ldmatrix lane addressing
    const int a_row  = wm + (lane & 15);
    const int a_koff = (lane >> 4) * 8;
    const int b_row  = wn + ((lane >> 4) * 8) + (lane & 7);   // two n-groups per x4
    const int b_koff = ((lane >> 3) & 1) * 8;

    for (int ch = 0; ch < I_ / XKC; ch++) {
        if (ch + 1 < I_ / XKC) { load_chunk((ch + 1) & 1, (ch + 1) * XKC); cp_wait<1>(); }
        else                   { cp_wait<0>(); }
        __syncthreads();
        const int buf = ch & 1;
        const __nv_bfloat16* ah_base = sa + (size_t)(buf * 2 + 0) * 128 * XPA;
        const __nv_bfloat16* al_base = sa + (size_t)(buf * 2 + 1) * 128 * XPA;
        const __nv_bfloat16* bh_base = sb + (size_t)(buf * 2 + 0) * 64 * XPA;
        const __nv_bfloat16* bl_base = sb + (size_t)(buf * 2 + 1) * 64 * XPA;
#pragma unroll
        for (int kk = 0; kk < XKC; kk += 16) {
            uint32_t ah[2][4], al[2][4];
#pragma unroll
            for (int fm = 0; fm < 2; fm++) {
                ldsm_x4(ah[fm][0], ah[fm][1], ah[fm][2], ah[fm][3],
                        sptr(ah_base + (a_row + fm * 16) * XPA + kk + a_koff));
                ldsm_x4(al[fm][0], al[fm][1], al[fm][2], al[fm][3],
                        sptr(al_base + (a_row + fm * 16) * XPA + kk + a_koff));
            }
            uint32_t bh[2][4], bl[2][4];
#pragma unroll
            for (int g = 0; g < 2; g++) {   // n-groups (0,8) and (16,24)
                ldsm_x4(bh[g][0], bh[g][1], bh[g][2], bh[g][3],
                        sptr(bh_base + (b_row + g * 16) * XPA + kk + b_koff));
                ldsm_x4(bl[g][0], bl[g][1], bl[g][2], bl[g][3],
                        sptr(bl_base + (b_row + g * 16) * XPA + kk + b_koff));
            }
#pragma unroll
            for (int fm = 0; fm < 2; fm++)
#pragma unroll
                for (int fn = 0; fn < 4; fn++) {
                    int g = fn >> 1, o = (fn & 1) * 2;
                    float* c = acc[fm][fn];
                    mma_bf16(c[0], c[1], c[2], c[3],
                             ah[fm][0], ah[fm][1], ah[fm][2], ah[fm][3],
                             bh[g][o], bh[g][o + 1]);
                    mma_bf16(c[0], c[1], c[2], c[3],
                             ah[fm][0], ah[fm][1], ah[fm][2], ah[fm][3],
                             bl[g][o], bl[g][o + 1]);
                    mma_bf16(c[0], c[1], c[2], c[3],
                             al[fm][0], al[fm][1], al[fm][2], al[fm][3],
                             bh[g][o], bh[g][o + 1]);
                }
        }
        __syncthreads();
    }

    // epilogue
    const int r = lane >> 2;
    const int cp = (lane & 3) * 2;
#pragma unroll
    for (int fn = 0; fn < 4; fn++) {
        int col = n0 + wn + fn * 8 + cp;
        float2 bias = *(const float2*)(bx + col);
#pragma unroll
        for (int fm = 0; fm < 2; fm++) {
            int mr = m0 + wm + fm * 16 + r;
            float2 v0 = make_float2(acc[fm][fn][0] + bias.x, acc[fm][fn][1] + bias.y);
            float2 v1 = make_float2(acc[fm][fn][2] + bias.x, acc[fm][fn][3] + bias.y);
            *(float2*)(g_xproj + (size_t)mr * H_ + col) = v0;
            *(float2*)(g_xproj + (size_t)(mr + 8) * H_ + col) = v1;
        }
    }
}

// ---------------------------------------------------------------------------
// Persistent recurrence kernel. 128 CTAs (32 j-tiles x 4 b-tiles), 256 threads.
// Wh slice (32 j-rows, hi/lo) resident in SMEM; h streamed hi/lo via cp.async.
// ---------------------------------------------------------------------------
#define RKC    128
#define WPITCH 1032   // halves: 1024 + 8 pad -> 2064B rows, conflict-free ldmatrix
#define SPITCH 136    // halves: 128 + 8 pad  -> 272B rows, conflict-free ldmatrix

__global__ __launch_bounds__(256) void k_rnn(const float* __restrict__ Wh) {
    extern __shared__ __nv_bfloat16 dsm[];
    __nv_bfloat16* ws_hi = dsm;                       // [32][WPITCH]
    __nv_bfloat16* ws_lo = dsm + 32 * WPITCH;
    __nv_bfloat16* shb   = dsm + 2 * 32 * WPITCH;     // [buf][sp][32*SPITCH]

    const int tid = threadIdx.x;
    const int lane = tid & 31, wid = tid >> 5;
    const int jt = blockIdx.x & 31, bt = blockIdx.x >> 5;
    const int jb = jt * 32, bb = bt * 32;

    // load + split resident Wh slice (32 rows x 1024)
    for (int u = tid; u < 32 * (H_ / 4); u += 256) {
        int row = u >> 8;              // H_/4 = 256
        int c4 = (u & 255) * 4;
        float4 v = *(const float4*)(Wh + (size_t)(jb + row) * H_ + c4);
        __nv_bfloat16 h0, l0, h1, l1, h2, l2, h3, l3;
        split2(v.x, h0, l0); split2(v.y, h1, l1);
        split2(v.z, h2, l2); split2(v.w, h3, l3);
        __nv_bfloat16* dh = ws_hi + row * WPITCH + c4;
        __nv_bfloat16* dl = ws_lo + row * WPITCH + c4;
        dh[0] = h0; dh[1] = h1; dh[2] = h2; dh[3] = h3;
        dl[0] = l0; dl[1] = l1; dl[2] = l2; dl[3] = l3;
    }

    // t = 0: h1 = tanh(xproj[0])  (h0 = 0)
    {
        int row = tid >> 3;            // 32 rows
        int c4 = (tid & 7) * 4;        // 32 cols in steps of 4
        float4 v = *(const float4*)(g_xproj + (size_t)(bb + row) * H_ + jb + c4);
        float t0 = tanhf(v.x), t1 = tanhf(v.y), t2 = tanhf(v.z), t3 = tanhf(v.w);
        __nv_bfloat16 h0, l0, h1, l1, h2, l2, h3, l3;
        split2(t0, h0, l0); split2(t1, h1, l1);
        split2(t2, h2, l2); split2(t3, h3, l3);
        __nv_bfloat16* dh = g_hbf[1][0] + (size_t)(bb + row) * H_ + jb + c4;
        __nv_bfloat16* dl = g_hbf[1][1] + (size_t)(bb + row) * H_ + jb + c4;
        __nv_bfloat162 p;
        p.x = h0; p.y = h1; *(__nv_bfloat162*)(dh)     = p;
        p.x = h2; p.y = h3; *(__nv_bfloat162*)(dh + 2) = p;
        p.x = l0; p.y = l1; *(__nv_bfloat162*)(dl)     = p;
        p.x = l2; p.y = l3; *(__nv_bfloat162*)(dl + 2) = p;
    }
    __threadfence();
    gridbar();

    const int wm = (wid & 1) * 16;     // warp m (b) offset in 32
    const int wn = (wid >> 1) * 8;     // warp n (j) offset in 32

    // ldmatrix lane addressing
    const int a_row  = wm + (lane & 15);
    const int a_koff = (lane >> 4) * 8;
    const int b_row  = wn + (lane & 7);
    const int b_koff = (lane >> 3) * 8;    // k32-wide x4: tiles k0,k8,k16,k24

    const int r = lane >> 2;
    const int cp = (lane & 3) * 2;
    const int bg0 = bb + wm + r;
    const int jg  = jb + wn + cp;

    for (int t = 1; t < S_; t++) {
        // prefetch xproj fragment for epilogue (hides DRAM latency behind GEMM)
        const float* xp = g_xproj + (size_t)t * B_ * H_;
        float2 xv0 = __ldg((const float2*)(xp + (size_t)bg0 * H_ + jg));
        float2 xv1 = __ldg((const float2*)(xp + (size_t)(bg0 + 8) * H_ + jg));

        const __nv_bfloat16* hin_hi = g_hbf[t & 1][0];
        const __nv_bfloat16* hin_lo = g_hbf[t & 1][1];

        // prologue chunk 0
        {
#pragma unroll
            for (int sp = 0; sp < 2; sp++) {
                const __nv_bfloat16* src = sp ? hin_lo : hin_hi;
                __nv_bfloat16* dst = shb + (size_t)sp * 32 * SPITCH;
#pragma unroll
                for (int q = 0; q < 2; q++) {
                    int u = tid + q * 256;        // 512 units: 32 rows x 16
                    int row = u >> 4, c16 = (u & 15) * 8;
                    cp_async16(dst + row * SPITCH + c16,
                               src + (size_t)(bb + row) * H_ + c16);
                }
            }
            cp_commit();
        }

        float ca[4] = {0, 0, 0, 0}, cbv[4] = {0, 0, 0, 0}, cc[4] = {0, 0, 0, 0};

        for (int ch = 0; ch < H_ / RKC; ch++) {
            if (ch + 1 < H_ / RKC) {
                int k0 = (ch + 1) * RKC;
                int nb = (ch + 1) & 1;
#pragma unroll
                for (int sp = 0; sp < 2; sp++) {
                    const __nv_bfloat16* src = sp ? hin_lo : hin_hi;
                    __nv_bfloat16* dst = shb + (size_t)(nb * 2 + sp) * 32 * SPITCH;
#pragma unroll
                    for (int q = 0; q < 2; q++) {
                        int u = tid + q * 256;
                        int row = u >> 4, c16 = (u & 15) * 8;
                        cp_async16(dst + row * SPITCH + c16,
                                   src + (size_t)(bb + row) * H_ + k0 + c16);
                    }
                }
                cp_commit();
                cp_wait<1>();
            } else {
                cp_wait<0>();
            }
            __syncthreads();
            const int buf = ch & 1;
            const __nv_bfloat16* ah_base = shb + (size_t)(buf * 2 + 0) * 32 * SPITCH;
            const __nv_bfloat16* al_base = shb + (size_t)(buf * 2 + 1) * 32 * SPITCH;
#pragma unroll
            for (int g = 0; g < 4; g++) {   // k32 groups within 128-chunk
                int kb = ch * RKC + g * 32; // global k for resident Wh
                int ks = g * 32;            // k within streamed chunk
                uint32_t bh0, bh1, bh2, bh3, bl0, bl1, bl2, bl3;
                ldsm_x4(bh0, bh1, bh2, bh3, sptr(ws_hi + b_row * WPITCH + kb + b_koff));
                ldsm_x4(bl0, bl1, bl2, bl3, sptr(ws_lo + b_row * WPITCH + kb + b_koff));
                uint32_t a0h[4], a1h[4], a0l[4], a1l[4];
                ldsm_x4(a0h[0], a0h[1], a0h[2], a0h[3],
                        sptr(ah_base + a_row * SPITCH + ks + a_koff));
                ldsm_x4(a1h[0], a1h[1], a1h[2], a1h[3],
                        sptr(ah_base + a_row * SPITCH + ks + 16 + a_koff));
                ldsm_x4(a0l[0], a0l[1], a0l[2], a0l[3],
                        sptr(al_base + a_row * SPITCH + ks + a_koff));
                ldsm_x4(a1l[0], a1l[1], a1l[2], a1l[3],
                        sptr(al_base + a_row * SPITCH + ks + 16 + a_koff));
                // k16 #1: B regs (bh0,bh1)/(bl0,bl1); k16 #2: (bh2,bh3)/(bl2,bl3)
                mma_bf16(ca[0], ca[1], ca[2], ca[3], a0h[0], a0h[1], a0h[2], a0h[3], bh0, bh1);
                mma_bf16(cbv[0], cbv[1], cbv[2], cbv[3], a0h[0], a0h[1], a0h[2], a0h[3], bl0, bl1);
                mma_bf16(cc[0], cc[1], cc[2], cc[3], a0l[0], a0l[1], a0l[2], a0l[3], bh0, bh1);
                mma_bf16(ca[0], ca[1], ca[2], ca[3], a1h[0], a1h[1], a1h[2], a1h[3], bh2, bh3);
                mma_bf16(cbv[0], cbv[1], cbv[2], cbv[3], a1h[0], a1h[1], a1h[2], a1h[3], bl2, bl3);
                mma_bf16(cc[0], cc[1], cc[2], cc[3], a1l[0], a1l[1], a1l[2], a1l[3], bh2, bh3);
            }
            __syncthreads();
        }

        // epilogue
        float z0 = tanhf(ca[0] + cbv[0] + cc[0] + xv0.x);
        float z1 = tanhf(ca[1] + cbv[1] + cc[1] + xv0.y);
        float z2 = tanhf(ca[2] + cbv[2] + cc[2] + xv1.x);
        float z3 = tanhf(ca[3] + cbv[3] + cc[3] + xv1.y);

        if (t < S_ - 1) {
            __nv_bfloat16* hout_hi = g_hbf[(t + 1) & 1][0];
            __nv_bfloat16* hout_lo = g_hbf[(t + 1) & 1][1];
            __nv_bfloat16 h0, l0, h1, l1;
            __nv_bfloat162 p;
            split2(z0, h0, l0); split2(z1, h1, l1);
            p.x = h0; p.y = h1; *(__nv_bfloat162*)(hout_hi + (size_t)bg0 * H_ + jg) = p;
            p.x = l0; p.y = l1; *(__nv_bfloat162*)(hout_lo + (size_t)bg0 * H_ + jg) = p;
            split2(z2, h0, l0); split2(z3, h1, l1);
            p.x = h0; p.y = h1; *(__nv_bfloat162*)(hout_hi + (size_t)(bg0 + 8) * H_ + jg) = p;
            p.x = l0; p.y = l1; *(__nv_bfloat162*)(hout_lo + (size_t)(bg0 + 8) * H_ + jg) = p;
            __threadfence();
            gridbar();
        } else {
            *(float2*)(g_hf + (size_t)bg0 * H_ + jg) = make_float2(z0, z1);
            *(float2*)(g_hf + (size_t)(bg0 + 8) * H_ + jg) = make_float2(z2, z3);
        }
    }
}

// ---------------------------------------------------------------------------
// Final projection (fp32 SIMT, tiny): out[b][o] = sum_k h[b][k]*Wp[o][k] + bp[o]
// ---------------------------------------------------------------------------
#define KC   64
#define SROW (KC + 4)

__global__ __launch_bounds__(256) void k_final(const float* __restrict__ Wp,
                                               const float* __restrict__ bp,
                                               float* __restrict__ out) {
    __shared__ float hs[2][32][SROW];
    __shared__ float ws[2][32][SROW];
    const int tid = threadIdx.x;
    const int jb = blockIdx.x * 32;
    const int bb = blockIdx.y * 32;
    const float* __restrict__ hin = g_hf;

    const int r0 = tid >> 4;
    const int c0 = (tid & 15) << 2;

    float4 acc00 = {0,0,0,0}, acc01 = {0,0,0,0}, acc10 = {0,0,0,0}, acc11 = {0,0,0,0};
    const int b0 = (tid >> 4) << 1;
    const int j0 = tid & 15;

    {
#pragma unroll
        for (int q = 0; q < 2; q++) {
            int row = r0 + q * 16;
            cp_async16(&hs[0][row][c0], hin + (size_t)(bb + row) * H_ + c0);
            cp_async16(&ws[0][row][c0], Wp  + (size_t)(jb + row) * H_ + c0);
        }
        cp_commit();
    }

    for (int c = 0; c < H_ / KC; c++) {
        if (c + 1 < H_ / KC) {
            int k0 = (c + 1) * KC;
            int nb = (c + 1) & 1;
#pragma unroll
            for (int q = 0; q < 2; q++) {
                int row = r0 + q * 16;
                cp_async16(&hs[nb][row][c0], hin + (size_t)(bb + row) * H_ + k0 + c0);
                cp_async16(&ws[nb][row][c0], Wp  + (size_t)(jb + row) * H_ + k0 + c0);
            }
            cp_commit();
            cp_wait<1>();
        } else {
            cp_wait<0>();
        }
        __syncthreads();
        const int buf = c & 1;
#pragma unroll
        for (int k4 = 0; k4 < KC; k4 += 4) {
            float4 a0 = *(const float4*)&hs[buf][b0    ][k4];
            float4 a1 = *(const float4*)&hs[buf][b0 + 1][k4];
            float4 w0 = *(const float4*)&ws[buf][j0     ][k4];
            float4 w1 = *(const float4*)&ws[buf][j0 + 16][k4];
            fma4(acc00, a0, w0); fma4(acc01, a0, w1);
            fma4(acc10, a1, w0); fma4(acc11, a1, w1);
        }
        __syncthreads();
    }

    {
        int bg = bb + b0, jg = jb + j0;
        float z;
        z = (acc00.x + acc00.y) + (acc00.z + acc00.w) + bp[jg];
        out[(size_t)bg * O_ + jg] = z;
        z = (acc01.x + acc01.y) + (acc01.z + acc01.w) + bp[jg + 16];
        out[(size_t)bg * O_ + jg + 16] = z;
        z = (acc10.x + acc10.y) + (acc10.z + acc10.w) + bp[jg];
        out[(size_t)(bg + 1) * O_ + jg] = z;
        z = (acc11.x + acc11.y) + (acc11.z + acc11.w) + bp[jg + 16];
        out[(size_t)(bg + 1) * O_ + jg + 16] = z;
    }
}

// ---------------------------------------------------------------------------
// launch
// ---------------------------------------------------------------------------
extern "C" void kernel_launch(void* const* d_in, const int* in_sizes, int n_in,
                              void* d_out, int out_size) {
    const float* x  = (const float*)d_in[0];
    const float* Wx = (const float*)d_in[1];
    const float* bx = (const float*)d_in[2];
    const float* Wh = (const float*)d_in[3];
    const float* Wp = (const float*)d_in[4];
    const float* bp = (const float*)d_in[5];
    float* out = (float*)d_out;

    const int XSMEM = (2 * 2 * 128 * XPA + 2 * 2 * 64 * XPA) * (int)sizeof(__nv_bfloat16);
    const int RSMEM = (2 * 32 * WPITCH + 2 * 2 * 32 * SPITCH) * (int)sizeof(__nv_bfloat16);
    cudaFuncSetAttribute(k_xproj_mma, cudaFuncAttributeMaxDynamicSharedMemorySize, XSMEM);
    cudaFuncSetAttribute(k_rnn, cudaFuncAttributeMaxDynamicSharedMemorySize, RSMEM);

    k_convert_x<<<(S_ * B_ * I_ / 4) / 256, 256>>>(x);
    k_convert_wx<<<(H_ * I_ / 4) / 256, 256>>>(Wx);
    k_xproj_mma<<<dim3(H_ / 64, (B_ * S_) / 128), 256, XSMEM>>>(bx);
    k_rnn<<<NCTA, 256, RSMEM>>>(Wh);
    k_final<<<dim3(O_ / 32, B_ / 32), 256>>>(Wp, bp, out);
}

// round 5
// speedup vs baseline: 2.9283x; 1.2654x over previous
#include <cuda_runtime.h>
#include <cuda_bf16.h>
#include <math.h>
#include <stdint.h>

#define B_   128
#define S_   512
#define I_   512
#define H_   1024
#define O_   512
#define NCTA 128

// ---------------------------------------------------------------------------
// device globals (allocation-free scratch)
// ---------------------------------------------------------------------------
__device__ __align__(256) float g_xproj[(size_t)S_ * B_ * H_];        // [m=s*B+b][h]
__device__ __align__(256) float g_hf[B_ * H_];                        // fp32 final h
__device__ __align__(256) __nv_bfloat16 g_hbf[2][2][B_ * H_];         // [pingpong][hi/lo][b][k]
__device__ __align__(256) __nv_bfloat16 g_xr[2][(size_t)S_ * B_ * I_];// [hi/lo][m=s*B+b][i]
__device__ __align__(256) __nv_bfloat16 g_Wxbf[2][(size_t)H_ * I_];   // [hi/lo][h][i]
__device__ unsigned g_barc = 0;
__device__ volatile unsigned g_barg = 0;

// ---------------------------------------------------------------------------
// helpers
// ---------------------------------------------------------------------------
__device__ __forceinline__ void cp_async16(void* s, const void* g) {
    uint32_t sa = (uint32_t)__cvta_generic_to_shared(s);
    asm volatile("cp.async.cg.shared.global [%0], [%1], 16;" :: "r"(sa), "l"(g));
}
__device__ __forceinline__ void cp_commit() { asm volatile("cp.async.commit_group;"); }
template <int N> __device__ __forceinline__ void cp_wait() {
    asm volatile("cp.async.wait_group %0;" :: "n"(N));
}
__device__ __forceinline__ uint32_t sptr(const void* p) {
    return (uint32_t)__cvta_generic_to_shared(p);
}
__device__ __forceinline__ void ldsm_x4(uint32_t& r0, uint32_t& r1, uint32_t& r2, uint32_t& r3,
                                        uint32_t addr) {
    asm volatile("ldmatrix.sync.aligned.m8n8.x4.shared.b16 {%0,%1,%2,%3}, [%4];"
                 : "=r"(r0), "=r"(r1), "=r"(r2), "=r"(r3) : "r"(addr));
}
__device__ __forceinline__ void mma_bf16(float& c0, float& c1, float& c2, float& c3,
                                         uint32_t a0, uint32_t a1, uint32_t a2, uint32_t a3,
                                         uint32_t b0, uint32_t b1) {
    asm volatile("mma.sync.aligned.m16n8k16.row.col.f32.bf16.bf16.f32 "
                 "{%0,%1,%2,%3}, {%4,%5,%6,%7}, {%8,%9}, {%0,%1,%2,%3};"
                 : "+f"(c0), "+f"(c1), "+f"(c2), "+f"(c3)
                 : "r"(a0), "r"(a1), "r"(a2), "r"(a3), "r"(b0), "r"(b1));
}
__device__ __forceinline__ void fma4(float4& acc, const float4 a, const float4 b) {
    acc.x = fmaf(a.x, b.x, acc.x);
    acc.y = fmaf(a.y, b.y, acc.y);
    acc.z = fmaf(a.z, b.z, acc.z);
    acc.w = fmaf(a.w, b.w, acc.w);
}
__device__ __forceinline__ void split2(float v, __nv_bfloat16& hi, __nv_bfloat16& lo) {
    hi = __float2bfloat16(v);
    lo = __float2bfloat16(v - __bfloat162float(hi));
}

// grid-wide barrier (all NCTA CTAs co-resident)
__device__ __forceinline__ void gridbar() {
    __syncthreads();
    if (threadIdx.x == 0) {
        __threadfence();
        unsigned gen = g_barg;
        if (atomicAdd(&g_barc, 1u) == NCTA - 1) {
            g_barc = 0;
            __threadfence();
            g_barg = gen + 1;
        } else {
            while (g_barg == gen) { }
            __threadfence();
        }
    }
    __syncthreads();
}

__device__ __forceinline__ void groupbar(int ks) {
    asm volatile("bar.sync %0, 128;" :: "r"(ks + 1) : "memory");
}

// ---------------------------------------------------------------------------
// conversions: x -> reordered hi/lo bf16 [m=s*B+b][i]; Wx -> hi/lo
// ---------------------------------------------------------------------------
__global__ __launch_bounds__(256) void k_convert_x(const float* __restrict__ x) {
    int gid = blockIdx.x * blockDim.x + threadIdx.x;   // S*B*I/4 units
    int i4 = (gid & (I_ / 4 - 1)) * 4;
    int m  = gid >> 7;                                 // I_/4 = 128
    int s = m / B_, b = m % B_;
    float4 v = *(const float4*)(x + ((size_t)b * S_ + s) * I_ + i4);
    __nv_bfloat16 h0, l0, h1, l1, h2, l2, h3, l3;
    split2(v.x, h0, l0); split2(v.y, h1, l1);
    split2(v.z, h2, l2); split2(v.w, h3, l3);
    __nv_bfloat162 p;
    __nv_bfloat16* dh = g_xr[0] + (size_t)m * I_ + i4;
    __nv_bfloat16* dl = g_xr[1] + (size_t)m * I_ + i4;
    p.x = h0; p.y = h1; *(__nv_bfloat162*)(dh)     = p;
    p.x = h2; p.y = h3; *(__nv_bfloat162*)(dh + 2) = p;
    p.x = l0; p.y = l1; *(__nv_bfloat162*)(dl)     = p;
    p.x = l2; p.y = l3; *(__nv_bfloat162*)(dl + 2) = p;
}

__global__ __launch_bounds__(256) void k_convert_wx(const float* __restrict__ Wx) {
    int gid = blockIdx.x * blockDim.x + threadIdx.x;   // H*I/4 units
    int i = gid * 4;
    float4 v = *(const float4*)(Wx + i);
    __nv_bfloat16 h0, l0, h1, l1, h2, l2, h3, l3;
    split2(v.x, h0, l0); split2(v.y, h1, l1);
    split2(v.z, h2, l2); split2(v.w, h3, l3);
    __nv_bfloat162 p;
    p.x = h0; p.y = h1; *(__nv_bfloat162*)(g_Wxbf[0] + i)     = p;
    p.x = h2; p.y = h3; *(__nv_bfloat162*)(g_Wxbf[0] + i + 2) = p;
    p.x = l0; p.y = l1; *(__nv_bfloat162*)(g_Wxbf[1] + i)     = p;
    p.x = l2; p.y = l3; *(__nv_bfloat162*)(g_Wxbf[1] + i + 2) = p;
}

// ---------------------------------------------------------------------------
// xproj GEMM via bf16x2-split mma (unchanged from R4)
// ---------------------------------------------------------------------------
#define XKC  64
#define XPA  72

__global__ __launch_bounds__(256) void k_xproj_mma(const float* __restrict__ bx) {
    extern __shared__ __nv_bfloat16 dsm[];
    __nv_bfloat16* sa = dsm;
    __nv_bfloat16* sb = dsm + 2 * 2 * 128 * XPA;

    const int tid = threadIdx.x;
    const int lane = tid & 31, wid = tid >> 5;
    const int n0 = blockIdx.x * 64;
    const int m0 = blockIdx.y * 128;
    const int wm = (wid & 3) * 32;
    const int wn = (wid >> 2) * 32;

    float acc[2][4][4];
#pragma unroll
    for (int a = 0; a < 2; a++)
#pragma unroll
        for (int b = 0; b < 4; b++)
#pragma unroll
            for (int c = 0; c < 4; c++) acc[a][b][c] = 0.0f;

    auto load_chunk = [&](int buf, int k0) {
#pragma unroll
        for (int sp = 0; sp < 2; sp++) {
            __nv_bfloat16* da = sa + (size_t)(buf * 2 + sp) * 128 * XPA;
            const __nv_bfloat16* ga = g_xr[sp];
#pragma unroll
            for (int q = 0; q < 4; q++) {
                int u = tid + q * 256;
                int row = u >> 3, c16 = (u & 7) * 8;
                cp_async16(da + row * XPA + c16,
                           ga + (size_t)(m0 + row) * I_ + k0 + c16);
            }
            __nv_bfloat16* db = sb + (size_t)(buf * 2 + sp) * 64 * XPA;
            const __nv_bfloat16* gb = g_Wxbf[sp];
#pragma unroll
            for (int q = 0; q < 2; q++) {
                int u = tid + q * 256;
                int row = u >> 3, c16 = (u & 7) * 8;
                cp_async16(db + row * XPA + c16,
                           gb + (size_t)(n0 + row) * I_ + k0 + c16);
            }
        }
        cp_commit();
    };

    load_chunk(0, 0);

    const int a_row  = wm + (lane & 15);
    const int a_koff = (lane >> 4) * 8;
    const int b_row  = wn + ((lane >> 4) * 8) + (lane & 7);
    const int b_koff = ((lane >> 3) & 1) * 8;

    for (int ch = 0; ch < I_ / XKC; ch++) {
        if (ch + 1 < I_ / XKC) { load_chunk((ch + 1) & 1, (ch + 1) * XKC); cp_wait<1>(); }
        else                   { cp_wait<0>(); }
        __syncthreads();
        const int buf = ch & 1;
        const __nv_bfloat16* ah_base = sa + (size_t)(buf * 2 + 0) * 128 * XPA;
        const __nv_bfloat16* al_base = sa + (size_t)(buf * 2 + 1) * 128 * XPA;
        const __nv_bfloat16* bh_base = sb + (size_t)(buf * 2 + 0) * 64 * XPA;
        const __nv_bfloat16* bl_base = sb + (size_t)(buf * 2 + 1) * 64 * XPA;
#pragma unroll
        for (int kk = 0; kk < XKC; kk += 16) {
            uint32_t ah[2][4], al[2][4];
#pragma unroll
            for (int fm = 0; fm < 2; fm++) {
                ldsm_x4(ah[fm][0], ah[fm][1], ah[fm][2], ah[fm][3],
                        sptr(ah_base + (a_row + fm * 16) * XPA + kk + a_koff));
                ldsm_x4(al[fm][0], al[fm][1], al[fm][2], al[fm][3],
                        sptr(al_base + (a_row + fm * 16) * XPA + kk + a_koff));
            }
            uint32_t bh[2][4], bl[2][4];
#pragma unroll
            for (int g = 0; g < 2; g++) {
                ldsm_x4(bh[g][0], bh[g][1], bh[g][2], bh[g][3],
                        sptr(bh_base + (b_row + g * 16) * XPA + kk + b_koff));
                ldsm_x4(bl[g][0], bl[g][1], bl[g][2], bl[g][3],
                        sptr(bl_base + (b_row + g * 16) * XPA + kk + b_koff));
            }
#pragma unroll
            for (int fm = 0; fm < 2; fm++)
#pragma unroll
                for (int fn = 0; fn < 4; fn++) {
                    int g = fn >> 1, o = (fn & 1) * 2;
                    float* c = acc[fm][fn];
                    mma_bf16(c[0], c[1], c[2], c[3],
                             ah[fm][0], ah[fm][1], ah[fm][2], ah[fm][3],
                             bh[g][o], bh[g][o + 1]);
                    mma_bf16(c[0], c[1], c[2], c[3],
                             ah[fm][0], ah[fm][1], ah[fm][2], ah[fm][3],
                             bl[g][o], bl[g][o + 1]);
                    mma_bf16(c[0], c[1], c[2], c[3],
                             al[fm][0], al[fm][1], al[fm][2], al[fm][3],
                             bh[g][o], bh[g][o + 1]);
                }
        }
        __syncthreads();
    }

    const int r = lane >> 2;
    const int cp = (lane & 3) * 2;
#pragma unroll
    for (int fn = 0; fn < 4; fn++) {
        int col = n0 + wn + fn * 8 + cp;
        float2 bias = *(const float2*)(bx + col);
#pragma unroll
        for (int fm = 0; fm < 2; fm++) {
            int mr = m0 + wm + fm * 16 + r;
            float2 v0 = make_float2(acc[fm][fn][0] + bias.x, acc[fm][fn][1] + bias.y);
            float2 v1 = make_float2(acc[fm][fn][2] + bias.x, acc[fm][fn][3] + bias.y);
            *(float2*)(g_xproj + (size_t)mr * H_ + col) = v0;
            *(float2*)(g_xproj + (size_t)(mr + 8) * H_ + col) = v1;
        }
    }
}

// ---------------------------------------------------------------------------
// Persistent recurrence kernel v2.
// 128 CTAs (32 j x 4 b), 256 thr = 4 n-warps x 2 K-half groups.
// Wh fragments register-resident; h streamed per K-half in 2 sub-chunks.
// ---------------------------------------------------------------------------
#define PIT 264   // halves per SMEM row (256 + 8), conflict-free ldmatrix

__global__ __launch_bounds__(256, 1) void k_rnn(const float* __restrict__ Wh) {
    extern __shared__ __nv_bfloat16 dsm[];
    // 8 planes [ (ks*2+sub)*2+sp ][32][PIT], then reduction buffer
    float* red = (float*)(dsm + 8 * 32 * PIT);   // [8][128] floats, i-major

    const int tid = threadIdx.x;
    const int lane = tid & 31, wid = tid >> 5;
    const int ks = wid >> 2;          // K-half
    const int nw = wid & 3;           // n-warp (8 j-cols)
    const int gtid = tid & 127;
    const int jt = blockIdx.x & 31, bt = blockIdx.x >> 5;
    const int jb = jt * 32, bb = bt * 32;

    // --- stage this group's Wh K-half into SMEM (split hi/lo) ---
    {
        const int kbase = ks * 512;
#pragma unroll
        for (int sub = 0; sub < 2; sub++) {
            __nv_bfloat16* dh = dsm + ((ks * 2 + sub) * 2 + 0) * 32 * PIT;
            __nv_bfloat16* dl = dsm + ((ks * 2 + sub) * 2 + 1) * 32 * PIT;
#pragma unroll
            for (int q = 0; q < 16; q++) {
                int u = gtid + q * 128;          // 2048 float4 units
                int row = u >> 6;
                int c4 = (u & 63) * 4;
                float4 v = *(const float4*)(Wh + (size_t)(jb + row) * H_ + kbase + sub * 256 + c4);
                __nv_bfloat16 h0, l0, h1, l1, h2, l2, h3, l3;
                split2(v.x, h0, l0); split2(v.y, h1, l1);
                split2(v.z, h2, l2); split2(v.w, h3, l3);
                __nv_bfloat16* ph = dh + row * PIT + c4;
                __nv_bfloat16* pl = dl + row * PIT + c4;
                ph[0] = h0; ph[1] = h1; ph[2] = h2; ph[3] = h3;
                pl[0] = l0; pl[1] = l1; pl[2] = l2; pl[3] = l3;
            }
        }
    }
    __syncthreads();

    // --- extract register-resident Wh fragments (n8 x K512 per warp) ---
    const int b_row  = nw * 8 + (lane & 7);
    const int b_koff = (lane >> 3) * 8;
    uint32_t bfh[16][4], bfl[16][4];
#pragma unroll
    for (int g = 0; g < 16; g++) {
        int sub = g >> 3, col = (g & 7) * 32 + b_koff;
        const __nv_bfloat16* ph = dsm + ((ks * 2 + sub) * 2 + 0) * 32 * PIT;
        const __nv_bfloat16* pl = dsm + ((ks * 2 + sub) * 2 + 1) * 32 * PIT;
        ldsm_x4(bfh[g][0], bfh[g][1], bfh[g][2], bfh[g][3], sptr(ph + b_row * PIT + col));
        ldsm_x4(bfl[g][0], bfl[g][1], bfl[g][2], bfl[g][3], sptr(pl + b_row * PIT + col));
    }
    __syncthreads();

    // --- t = 0: h(1) = tanh(xproj[0]) ---
    {
        int row = tid >> 3;
        int c4 = (tid & 7) * 4;
        float4 v = *(const float4*)(g_xproj + (size_t)(bb + row) * H_ + jb + c4);
        float t0 = tanhf(v.x), t1 = tanhf(v.y), t2 = tanhf(v.z), t3 = tanhf(v.w);
        __nv_bfloat16 h0, l0, h1, l1, h2, l2, h3, l3;
        split2(t0, h0, l0); split2(t1, h1, l1);
        split2(t2, h2, l2); split2(t3, h3, l3);
        __nv_bfloat16* dh = g_hbf[1][0] + (size_t)(bb + row) * H_ + jb + c4;
        __nv_bfloat16* dl = g_hbf[1][1] + (size_t)(bb + row) * H_ + jb + c4;
        __nv_bfloat162 p;
        p.x = h0; p.y = h1; *(__nv_bfloat162*)(dh)     = p;
        p.x = h2; p.y = h3; *(__nv_bfloat162*)(dh + 2) = p;
        p.x = l0; p.y = l1; *(__nv_bfloat162*)(dl)     = p;
        p.x = l2; p.y = l3; *(__nv_bfloat162*)(dl + 2) = p;
    }
    __threadfence();
    gridbar();

    const int a_row  = lane & 15;
    const int a_koff = (lane >> 4) * 8;
    const int r   = lane >> 2;
    const int cp2 = (lane & 3) * 2;
    const int jg  = jb + nw * 8 + cp2;
    const int kbase = ks * 512;

    for (int t = 1; t < S_; t++) {
        const __nv_bfloat16* hin_hi = g_hbf[t & 1][0];
        const __nv_bfloat16* hin_lo = g_hbf[t & 1][1];

        // prefetch xproj fragment (epilogue warps only)
        float2 xv0, xv1, xv2, xv3;
        if (ks == 0) {
            const float* xp = g_xproj + (size_t)t * B_ * H_;
            xv0 = __ldg((const float2*)(xp + (size_t)(bb + r     ) * H_ + jg));
            xv1 = __ldg((const float2*)(xp + (size_t)(bb + r +  8) * H_ + jg));
            xv2 = __ldg((const float2*)(xp + (size_t)(bb + r + 16) * H_ + jg));
            xv3 = __ldg((const float2*)(xp + (size_t)(bb + r + 24) * H_ + jg));
        }

        // issue both sub-chunk loads (this group's K-half only)
#pragma unroll
        for (int sub = 0; sub < 2; sub++) {
#pragma unroll
            for (int sp = 0; sp < 2; sp++) {
                const __nv_bfloat16* src = sp ? hin_lo : hin_hi;
                __nv_bfloat16* dst = dsm + ((ks * 2 + sub) * 2 + sp) * 32 * PIT;
#pragma unroll
                for (int q = 0; q < 8; q++) {
                    int u = gtid + q * 128;      // 1024 units of 8 halves
                    int row = u >> 5;
                    int c8 = (u & 31) * 8;
                    cp_async16(dst + row * PIT + c8,
                               src + (size_t)(bb + row) * H_ + kbase + sub * 256 + c8);
                }
            }
            cp_commit();
        }

        float c1[2][4] = {0}, c2[2][4] = {0}, c3[2][4] = {0};

        auto do_group = [&](int g) {
            const int sub = g >> 3;
            const int cb = (g & 7) * 32;
            const __nv_bfloat16* ph = dsm + ((ks * 2 + sub) * 2 + 0) * 32 * PIT;
            const __nv_bfloat16* pl = dsm + ((ks * 2 + sub) * 2 + 1) * 32 * PIT;
            uint32_t ah[2][2][4], al[2][2][4];
#pragma unroll
            for (int fm = 0; fm < 2; fm++)
#pragma unroll
                for (int kh = 0; kh < 2; kh++) {
                    ldsm_x4(ah[fm][kh][0], ah[fm][kh][1], ah[fm][kh][2], ah[fm][kh][3],
                            sptr(ph + (a_row + fm * 16) * PIT + cb + kh * 16 + a_koff));
                    ldsm_x4(al[fm][kh][0], al[fm][kh][1], al[fm][kh][2], al[fm][kh][3],
                            sptr(pl + (a_row + fm * 16) * PIT + cb + kh * 16 + a_koff));
                }
#pragma unroll
            for (int fm = 0; fm < 2; fm++)
#pragma unroll
                for (int kh = 0; kh < 2; kh++) {
                    mma_bf16(c1[fm][0], c1[fm][1], c1[fm][2], c1[fm][3],
                             ah[fm][kh][0], ah[fm][kh][1], ah[fm][kh][2], ah[fm][kh][3],
                             bfh[g][kh * 2], bfh[g][kh * 2 + 1]);
                    mma_bf16(c2[fm][0], c2[fm][1], c2[fm][2], c2[fm][3],
                             ah[fm][kh][0], ah[fm][kh][1], ah[fm][kh][2], ah[fm][kh][3],
                             bfl[g][kh * 2], bfl[g][kh * 2 + 1]);
                    mma_bf16(c3[fm][0], c3[fm][1], c3[fm][2], c3[fm][3],
                             al[fm][kh][0], al[fm][kh][1], al[fm][kh][2], al[fm][kh][3],
                             bfh[g][kh * 2], bfh[g][kh * 2 + 1]);
                }
        };

        cp_wait<1>();
        groupbar(ks);
#pragma unroll
        for (int g = 0; g < 8; g++) do_group(g);
        cp_wait<0>();
        groupbar(ks);
#pragma unroll
        for (int g = 8; g < 16; g++) do_group(g);

        // sum 3 terms
        float s[2][4];
#pragma unroll
        for (int fm = 0; fm < 2; fm++)
#pragma unroll
            for (int i = 0; i < 4; i++)
                s[fm][i] = c1[fm][i] + c2[fm][i] + c3[fm][i];

        // split-K reduction: ks1 -> SMEM, ks0 adds
        if (ks == 1) {
#pragma unroll
            for (int fm = 0; fm < 2; fm++)
#pragma unroll
                for (int i = 0; i < 4; i++)
                    red[(fm * 4 + i) * 128 + nw * 32 + lane] = s[fm][i];
        }
        __syncthreads();
        if (ks == 0) {
#pragma unroll
            for (int fm = 0; fm < 2; fm++)
#pragma unroll
                for (int i = 0; i < 4; i++)
                    s[fm][i] += red[(fm * 4 + i) * 128 + nw * 32 + lane];

            float z00 = tanhf(s[0][0] + xv0.x);
            float z01 = tanhf(s[0][1] + xv0.y);
            float z02 = tanhf(s[0][2] + xv1.x);
            float z03 = tanhf(s[0][3] + xv1.y);
            float z10 = tanhf(s[1][0] + xv2.x);
            float z11 = tanhf(s[1][1] + xv2.y);
            float z12 = tanhf(s[1][2] + xv3.x);
            float z13 = tanhf(s[1][3] + xv3.y);

            if (t < S_ - 1) {
                __nv_bfloat16* hout_hi = g_hbf[(t + 1) & 1][0];
                __nv_bfloat16* hout_lo = g_hbf[(t + 1) & 1][1];
                __nv_bfloat16 h0, l0, h1, l1;
                __nv_bfloat162 p;
                int rows[4] = {bb + r, bb + r + 8, bb + r + 16, bb + r + 24};
                float zz[4][2] = {{z00, z01}, {z02, z03}, {z10, z11}, {z12, z13}};
#pragma unroll
                for (int q = 0; q < 4; q++) {
                    split2(zz[q][0], h0, l0); split2(zz[q][1], h1, l1);
                    p.x = h0; p.y = h1;
                    *(__nv_bfloat162*)(hout_hi + (size_t)rows[q] * H_ + jg) = p;
                    p.x = l0; p.y = l1;
                    *(__nv_bfloat162*)(hout_lo + (size_t)rows[q] * H_ + jg) = p;
                }
            } else {
                *(float2*)(g_hf + (size_t)(bb + r     ) * H_ + jg) = make_float2(z00, z01);
                *(float2*)(g_hf + (size_t)(bb + r +  8) * H_ + jg) = make_float2(z02, z03);
                *(float2*)(g_hf + (size_t)(bb + r + 16) * H_ + jg) = make_float2(z10, z11);
                *(float2*)(g_hf + (size_t)(bb + r + 24) * H_ + jg) = make_float2(z12, z13);
            }
        }
        __threadfence();
        if (t < S_ - 1) gridbar();
    }
}

// ---------------------------------------------------------------------------
// Final projection (fp32 SIMT, tiny)
// ---------------------------------------------------------------------------
#define KC   64
#define SROW (KC + 4)

__global__ __launch_bounds__(256) void k_final(const float* __restrict__ Wp,
                                               const float* __restrict__ bp,
                                               float* __restrict__ out) {
    __shared__ float hs[2][32][SROW];
    __shared__ float ws[2][32][SROW];
    const int tid = threadIdx.x;
    const int jb = blockIdx.x * 32;
    const int bb = blockIdx.y * 32;
    const float* __restrict__ hin = g_hf;

    const int r0 = tid >> 4;
    const int c0 = (tid & 15) << 2;

    float4 acc00 = {0,0,0,0}, acc01 = {0,0,0,0}, acc10 = {0,0,0,0}, acc11 = {0,0,0,0};
    const int b0 = (tid >> 4) << 1;
    const int j0 = tid & 15;

    {
#pragma unroll
        for (int q = 0; q < 2; q++) {
            int row = r0 + q * 16;
            cp_async16(&hs[0][row][c0], hin + (size_t)(bb + row) * H_ + c0);
            cp_async16(&ws[0][row][c0], Wp  + (size_t)(jb + row) * H_ + c0);
        }
        cp_commit();
    }

    for (int c = 0; c < H_ / KC; c++) {
        if (c + 1 < H_ / KC) {
            int k0 = (c + 1) * KC;
            int nb = (c + 1) & 1;
#pragma unroll
            for (int q = 0; q < 2; q++) {
                int row = r0 + q * 16;
                cp_async16(&hs[nb][row][c0], hin + (size_t)(bb + row) * H_ + k0 + c0);
                cp_async16(&ws[nb][row][c0], Wp  + (size_t)(jb + row) * H_ + k0 + c0);
            }
            cp_commit();
            cp_wait<1>();
        } else {
            cp_wait<0>();
        }
        __syncthreads();
        const int buf = c & 1;
#pragma unroll
        for (int k4 = 0; k4 < KC; k4 += 4) {
            float4 a0 = *(const float4*)&hs[buf][b0    ][k4];
            float4 a1 = *(const float4*)&hs[buf][b0 + 1][k4];
            float4 w0 = *(const float4*)&ws[buf][j0     ][k4];
            float4 w1 = *(const float4*)&ws[buf][j0 + 16][k4];
            fma4(acc00, a0, w0); fma4(acc01, a0, w1);
            fma4(acc10, a1, w0); fma4(acc11, a1, w1);
        }
        __syncthreads();
    }

    {
        int bg = bb + b0, jg = jb + j0;
        float z;
        z = (acc00.x + acc00.y) + (acc00.z + acc00.w) + bp[jg];
        out[(size_t)bg * O_ + jg] = z;
        z = (acc01.x + acc01.y) + (acc01.z + acc01.w) + bp[jg + 16];
        out[(size_t)bg * O_ + jg + 16] = z;
        z = (acc10.x + acc10.y) + (acc10.z + acc10.w) + bp[jg];
        out[(size_t)(bg + 1) * O_ + jg] = z;
        z = (acc11.x + acc11.y) + (acc11.z + acc11.w) + bp[jg + 16];
        out[(size_t)(bg + 1) * O_ + jg + 16] = z;
    }
}

// ---------------------------------------------------------------------------
// launch
// ---------------------------------------------------------------------------
extern "C" void kernel_launch(void* const* d_in, const int* in_sizes, int n_in,
                              void* d_out, int out_size) {
    const float* x  = (const float*)d_in[0];
    const float* Wx = (const float*)d_in[1];
    const float* bx = (const float*)d_in[2];
    const float* Wh = (const float*)d_in[3];
    const float* Wp = (const float*)d_in[4];
    const float* bp = (const float*)d_in[5];
    float* out = (float*)d_out;

    const int XSMEM = (2 * 2 * 128 * XPA + 2 * 2 * 64 * XPA) * (int)sizeof(__nv_bfloat16);
    const int RSMEM = 8 * 32 * PIT * (int)sizeof(__nv_bfloat16) + 8 * 128 * (int)sizeof(float);
    cudaFuncSetAttribute(k_xproj_mma, cudaFuncAttributeMaxDynamicSharedMemorySize, XSMEM);
    cudaFuncSetAttribute(k_rnn, cudaFuncAttributeMaxDynamicSharedMemorySize, RSMEM);

    k_convert_x<<<(S_ * B_ * I_ / 4) / 256, 256>>>(x);
    k_convert_wx<<<(H_ * I_ / 4) / 256, 256>>>(Wx);
    k_xproj_mma<<<dim3(H_ / 64, (B_ * S_) / 128), 256, XSMEM>>>(bx);
    k_rnn<<<NCTA, 256, RSMEM>>>(Wh);
    k_final<<<dim3(O_ / 32, B_ / 32), 256>>>(Wp, bp, out);
}

// round 6
// speedup vs baseline: 3.4696x; 1.1848x over previous
#include <cuda_runtime.h>
#include <cuda_bf16.h>
#include <math.h>
#include <stdint.h>

#define B_   128
#define S_   512
#define I_   512
#define H_   1024
#define O_   512
#define NCTA 128

// ---------------------------------------------------------------------------
// device globals (allocation-free scratch)
// ---------------------------------------------------------------------------
__device__ __align__(256) float g_xproj[(size_t)S_ * B_ * H_];        // [m=s*B+b][h]
__device__ __align__(256) float g_hf[B_ * H_];                        // fp32 final h
__device__ __align__(256) __nv_bfloat16 g_hbf[2][2][B_ * H_];         // [pingpong][hi/lo][b][k]
__device__ __align__(256) __nv_bfloat16 g_xr[2][(size_t)S_ * B_ * I_];// [hi/lo][m=s*B+b][i]
__device__ __align__(256) __nv_bfloat16 g_Wxbf[2][(size_t)H_ * I_];   // [hi/lo][h][i]
__device__ unsigned g_gbar[4];                                        // per-bt-group barrier

// ---------------------------------------------------------------------------
// helpers
// ---------------------------------------------------------------------------
__device__ __forceinline__ void cp_async16(void* s, const void* g) {
    uint32_t sa = (uint32_t)__cvta_generic_to_shared(s);
    asm volatile("cp.async.cg.shared.global [%0], [%1], 16;" :: "r"(sa), "l"(g));
}
__device__ __forceinline__ void cp_commit() { asm volatile("cp.async.commit_group;"); }
template <int N> __device__ __forceinline__ void cp_wait() {
    asm volatile("cp.async.wait_group %0;" :: "n"(N));
}
__device__ __forceinline__ uint32_t sptr(const void* p) {
    return (uint32_t)__cvta_generic_to_shared(p);
}
__device__ __forceinline__ void ldsm_x4(uint32_t& r0, uint32_t& r1, uint32_t& r2, uint32_t& r3,
                                        uint32_t addr) {
    asm volatile("ldmatrix.sync.aligned.m8n8.x4.shared.b16 {%0,%1,%2,%3}, [%4];"
                 : "=r"(r0), "=r"(r1), "=r"(r2), "=r"(r3) : "r"(addr));
}
__device__ __forceinline__ void mma_bf16(float& c0, float& c1, float& c2, float& c3,
                                         uint32_t a0, uint32_t a1, uint32_t a2, uint32_t a3,
                                         uint32_t b0, uint32_t b1) {
    asm volatile("mma.sync.aligned.m16n8k16.row.col.f32.bf16.bf16.f32 "
                 "{%0,%1,%2,%3}, {%4,%5,%6,%7}, {%8,%9}, {%0,%1,%2,%3};"
                 : "+f"(c0), "+f"(c1), "+f"(c2), "+f"(c3)
                 : "r"(a0), "r"(a1), "r"(a2), "r"(a3), "r"(b0), "r"(b1));
}
__device__ __forceinline__ void fma4(float4& acc, const float4 a, const float4 b) {
    acc.x = fmaf(a.x, b.x, acc.x);
    acc.y = fmaf(a.y, b.y, acc.y);
    acc.z = fmaf(a.z, b.z, acc.z);
    acc.w = fmaf(a.w, b.w, acc.w);
}
__device__ __forceinline__ void split2(float v, __nv_bfloat16& hi, __nv_bfloat16& lo) {
    hi = __float2bfloat16(v);
    lo = __float2bfloat16(v - __bfloat162float(hi));
}
__device__ __forceinline__ void bar_arrive(unsigned* p) {
    asm volatile("red.release.gpu.global.add.u32 [%0], 1;" :: "l"(p) : "memory");
}
__device__ __forceinline__ void bar_wait(unsigned* p, unsigned target) {
    unsigned v;
    do {
        asm volatile("ld.acquire.gpu.global.u32 %0, [%1];" : "=r"(v) : "l"(p) : "memory");
    } while ((int)(v - target) < 0);
}
__device__ __forceinline__ void groupbar(int ks) {
    asm volatile("bar.sync %0, 128;" :: "r"(ks + 1) : "memory");
}

// ---------------------------------------------------------------------------
// conversions: x -> reordered hi/lo bf16 [m=s*B+b][i]; Wx -> hi/lo
// ---------------------------------------------------------------------------
__global__ __launch_bounds__(256) void k_convert_x(const float* __restrict__ x) {
    int gid = blockIdx.x * blockDim.x + threadIdx.x;   // S*B*I/4 units
    if (gid < 4) g_gbar[gid] = 0;                      // reset barriers each launch
    int i4 = (gid & (I_ / 4 - 1)) * 4;
    int m  = gid >> 7;                                 // I_/4 = 128
    int s = m / B_, b = m % B_;
    float4 v = *(const float4*)(x + ((size_t)b * S_ + s) * I_ + i4);
    __nv_bfloat16 h0, l0, h1, l1, h2, l2, h3, l3;
    split2(v.x, h0, l0); split2(v.y, h1, l1);
    split2(v.z, h2, l2); split2(v.w, h3, l3);
    __nv_bfloat162 p;
    __nv_bfloat16* dh = g_xr[0] + (size_t)m * I_ + i4;
    __nv_bfloat16* dl = g_xr[1] + (size_t)m * I_ + i4;
    p.x = h0; p.y = h1; *(__nv_bfloat162*)(dh)     = p;
    p.x = h2; p.y = h3; *(__nv_bfloat162*)(dh + 2) = p;
    p.x = l0; p.y = l1; *(__nv_bfloat162*)(dl)     = p;
    p.x = l2; p.y = l3; *(__nv_bfloat162*)(dl + 2) = p;
}

__global__ __launch_bounds__(256) void k_convert_wx(const float* __restrict__ Wx) {
    int gid = blockIdx.x * blockDim.x + threadIdx.x;   // H*I/4 units
    int i = gid * 4;
    float4 v = *(const float4*)(Wx + i);
    __nv_bfloat16 h0, l0, h1, l1, h2, l2, h3, l3;
    split2(v.x, h0, l0); split2(v.y, h1, l1);
    split2(v.z, h2, l2); split2(v.w, h3, l3);
    __nv_bfloat162 p;
    p.x = h0; p.y = h1; *(__nv_bfloat162*)(g_Wxbf[0] + i)     = p;
    p.x = h2; p.y = h3; *(__nv_bfloat162*)(g_Wxbf[0] + i + 2) = p;
    p.x = l0; p.y = l1; *(__nv_bfloat162*)(g_Wxbf[1] + i)     = p;
    p.x = l2; p.y = l3; *(__nv_bfloat162*)(g_Wxbf[1] + i + 2) = p;
}

// ---------------------------------------------------------------------------
// xproj GEMM via bf16x2-split mma (unchanged)
// ---------------------------------------------------------------------------
#define XKC  64
#define XPA  72

__global__ __launch_bounds__(256) void k_xproj_mma(const float* __restrict__ bx) {
    extern __shared__ __nv_bfloat16 dsm[];
    __nv_bfloat16* sa = dsm;
    __nv_bfloat16* sb = dsm + 2 * 2 * 128 * XPA;

    const int tid = threadIdx.x;
    const int lane = tid & 31, wid = tid >> 5;
    const int n0 = blockIdx.x * 64;
    const int m0 = blockIdx.y * 128;
    const int wm = (wid & 3) * 32;
    const int wn = (wid >> 2) * 32;

    float acc[2][4][4];
#pragma unroll
    for (int a = 0; a < 2; a++)
#pragma unroll
        for (int b = 0; b < 4; b++)
#pragma unroll
            for (int c = 0; c < 4; c++) acc[a][b][c] = 0.0f;

    auto load_chunk = [&](int buf, int k0) {
#pragma unroll
        for (int sp = 0; sp < 2; sp++) {
            __nv_bfloat16* da = sa + (size_t)(buf * 2 + sp) * 128 * XPA;
            const __nv_bfloat16* ga = g_xr[sp];
#pragma unroll
            for (int q = 0; q < 4; q++) {
                int u = tid + q * 256;
                int row = u >> 3, c16 = (u & 7) * 8;
                cp_async16(da + row * XPA + c16,
                           ga + (size_t)(m0 + row) * I_ + k0 + c16);
            }
            __nv_bfloat16* db = sb + (size_t)(buf * 2 + sp) * 64 * XPA;
            const __nv_bfloat16* gb = g_Wxbf[sp];
#pragma unroll
            for (int q = 0; q < 2; q++) {
                int u = tid + q * 256;
                int row = u >> 3, c16 = (u & 7) * 8;
                cp_async16(db + row * XPA + c16,
                           gb + (size_t)(n0 + row) * I_ + k0 + c16);
            }
        }
        cp_commit();
    };

    load_chunk(0, 0);

    const int a_row  = wm + (lane & 15);
    const int a_koff = (lane >> 4) * 8;
    const int b_row  = wn + ((lane >> 4) * 8) + (lane & 7);
    const int b_koff = ((lane >> 3) & 1) * 8;

    for (int ch = 0; ch < I_ / XKC; ch++) {
        if (ch + 1 < I_ / XKC) { load_chunk((ch + 1) & 1, (ch + 1) * XKC); cp_wait<1>(); }
        else                   { cp_wait<0>(); }
        __syncthreads();
        const int buf = ch & 1;
        const __nv_bfloat16* ah_base = sa + (size_t)(buf * 2 + 0) * 128 * XPA;
        const __nv_bfloat16* al_base = sa + (size_t)(buf * 2 + 1) * 128 * XPA;
        const __nv_bfloat16* bh_base = sb + (size_t)(buf * 2 + 0) * 64 * XPA;
        const __nv_bfloat16* bl_base = sb + (size_t)(buf * 2 + 1) * 64 * XPA;
#pragma unroll
        for (int kk = 0; kk < XKC; kk += 16) {
            uint32_t ah[2][4], al[2][4];
#pragma unroll
            for (int fm = 0; fm < 2; fm++) {
                ldsm_x4(ah[fm][0], ah[fm][1], ah[fm][2], ah[fm][3],
                        sptr(ah_base + (a_row + fm * 16) * XPA + kk + a_koff));
                ldsm_x4(al[fm][0], al[fm][1], al[fm][2], al[fm][3],
                        sptr(al_base + (a_row + fm * 16) * XPA + kk + a_koff));
            }
            uint32_t bh[2][4], bl[2][4];
#pragma unroll
            for (int g = 0; g < 2; g++) {
                ldsm_x4(bh[g][0], bh[g][1], bh[g][2], bh[g][3],
                        sptr(bh_base + (b_row + g * 16) * XPA + kk + b_koff));
                ldsm_x4(bl[g][0], bl[g][1], bl[g][2], bl[g][3],
                        sptr(bl_base + (b_row + g * 16) * XPA + kk + b_koff));
            }
#pragma unroll
            for (int fm = 0; fm < 2; fm++)
#pragma unroll
                for (int fn = 0; fn < 4; fn++) {
                    int g = fn >> 1, o = (fn & 1) * 2;
                    float* c = acc[fm][fn];
                    mma_bf16(c[0], c[1], c[2], c[3],
                             ah[fm][0], ah[fm][1], ah[fm][2], ah[fm][3],
                             bh[g][o], bh[g][o + 1]);
                    mma_bf16(c[0], c[1], c[2], c[3],
                             ah[fm][0], ah[fm][1], ah[fm][2], ah[fm][3],
                             bl[g][o], bl[g][o + 1]);
                    mma_bf16(c[0], c[1], c[2], c[3],
                             al[fm][0], al[fm][1], al[fm][2], al[fm][3],
                             bh[g][o], bh[g][o + 1]);
                }
        }
        __syncthreads();
    }

    const int r = lane >> 2;
    const int cp = (lane & 3) * 2;
#pragma unroll
    for (int fn = 0; fn < 4; fn++) {
        int col = n0 + wn + fn * 8 + cp;
        float2 bias = *(const float2*)(bx + col);
#pragma unroll
        for (int fm = 0; fm < 2; fm++) {
            int mr = m0 + wm + fm * 16 + r;
            float2 v0 = make_float2(acc[fm][fn][0] + bias.x, acc[fm][fn][1] + bias.y);
            float2 v1 = make_float2(acc[fm][fn][2] + bias.x, acc[fm][fn][3] + bias.y);
            *(float2*)(g_xproj + (size_t)mr * H_ + col) = v0;
            *(float2*)(g_xproj + (size_t)(mr + 8) * H_ + col) = v1;
        }
    }
}

// ---------------------------------------------------------------------------
// Persistent recurrence kernel v3.
// 128 CTAs (32 j x 4 b), 256 thr = 4 n-warps x 2 K-half groups.
// Wh register-resident; per-bt-group release/acquire barriers; cooperative epilogue.
// ---------------------------------------------------------------------------
#define PIT  264   // halves per SMEM row (256 + 8), conflict-free ldmatrix
#define REDP 33    // red row pitch (floats)

__global__ __launch_bounds__(256, 1) void k_rnn(const float* __restrict__ Wh) {
    extern __shared__ __nv_bfloat16 dsm[];
    float* red = (float*)(dsm + 8 * 32 * PIT);   // [2][32][REDP]

    const int tid = threadIdx.x;
    const int lane = tid & 31, wid = tid >> 5;
    const int ks = wid >> 2;          // K-half group
    const int nw = wid & 3;           // n-warp (8 j-cols)
    const int gtid = tid & 127;
    const int jt = blockIdx.x & 31, bt = blockIdx.x >> 5;
    const int jb = jt * 32, bb = bt * 32;
    unsigned* bar = &g_gbar[bt];

    // --- stage this group's Wh K-half into SMEM (split hi/lo) ---
    {
        const int kbase = ks * 512;
#pragma unroll
        for (int sub = 0; sub < 2; sub++) {
            __nv_bfloat16* dh = dsm + ((ks * 2 + sub) * 2 + 0) * 32 * PIT;
            __nv_bfloat16* dl = dsm + ((ks * 2 + sub) * 2 + 1) * 32 * PIT;
#pragma unroll
            for (int q = 0; q < 16; q++) {
                int u = gtid + q * 128;
                int row = u >> 6;
                int c4 = (u & 63) * 4;
                float4 v = *(const float4*)(Wh + (size_t)(jb + row) * H_ + kbase + sub * 256 + c4);
                __nv_bfloat16 h0, l0, h1, l1, h2, l2, h3, l3;
                split2(v.x, h0, l0); split2(v.y, h1, l1);
                split2(v.z, h2, l2); split2(v.w, h3, l3);
                __nv_bfloat16* ph = dh + row * PIT + c4;
                __nv_bfloat16* pl = dl + row * PIT + c4;
                ph[0] = h0; ph[1] = h1; ph[2] = h2; ph[3] = h3;
                pl[0] = l0; pl[1] = l1; pl[2] = l2; pl[3] = l3;
            }
        }
    }
    __syncthreads();

    // --- register-resident Wh fragments (n8 x K512 per warp) ---
    const int b_row  = nw * 8 + (lane & 7);
    const int b_koff = (lane >> 3) * 8;
    uint32_t bfh[16][4], bfl[16][4];
#pragma unroll
    for (int g = 0; g < 16; g++) {
        int sub = g >> 3, col = (g & 7) * 32 + b_koff;
        const __nv_bfloat16* ph = dsm + ((ks * 2 + sub) * 2 + 0) * 32 * PIT;
        const __nv_bfloat16* pl = dsm + ((ks * 2 + sub) * 2 + 1) * 32 * PIT;
        ldsm_x4(bfh[g][0], bfh[g][1], bfh[g][2], bfh[g][3], sptr(ph + b_row * PIT + col));
        ldsm_x4(bfl[g][0], bfl[g][1], bfl[g][2], bfl[g][3], sptr(pl + b_row * PIT + col));
    }
    __syncthreads();

    // epilogue mapping (all 256 threads, 4 outputs each)
    const int erow = tid >> 3;          // 0..31
    const int ecol = (tid & 7) * 4;     // 0..28

    // --- t = 0: h(1) = tanh(xproj[0]) ---
    {
        float4 v = *(const float4*)(g_xproj + (size_t)(bb + erow) * H_ + jb + ecol);
        float t0 = tanhf(v.x), t1 = tanhf(v.y), t2 = tanhf(v.z), t3 = tanhf(v.w);
        __nv_bfloat16 h0, l0, h1, l1, h2, l2, h3, l3;
        split2(t0, h0, l0); split2(t1, h1, l1);
        split2(t2, h2, l2); split2(t3, h3, l3);
        __nv_bfloat162 p01, p23;
        uint2 u;
        p01.x = h0; p01.y = h1; p23.x = h2; p23.y = h3;
        u.x = *(uint32_t*)&p01; u.y = *(uint32_t*)&p23;
        *(uint2*)(g_hbf[1][0] + (size_t)(bb + erow) * H_ + jb + ecol) = u;
        p01.x = l0; p01.y = l1; p23.x = l2; p23.y = l3;
        u.x = *(uint32_t*)&p01; u.y = *(uint32_t*)&p23;
        *(uint2*)(g_hbf[1][1] + (size_t)(bb + erow) * H_ + jb + ecol) = u;
    }
    __syncthreads();
    if (tid == 0) bar_arrive(bar);

    const int a_row  = lane & 15;
    const int a_koff = (lane >> 4) * 8;
    const int srow = lane >> 2;              // mma scatter row base
    const int scol = nw * 8 + (lane & 3) * 2;
    const int kbase = ks * 512;

    for (int t = 1; t < S_; t++) {
        // independent prefetch fills the barrier-wait shadow
        const float* xp = g_xproj + (size_t)t * B_ * H_;
        float4 xv = __ldg((const float4*)(xp + (size_t)(bb + erow) * H_ + jb + ecol));

        if (tid == 0) bar_wait(bar, 32u * (unsigned)t);
        __syncthreads();

        const __nv_bfloat16* hin_hi = g_hbf[t & 1][0];
        const __nv_bfloat16* hin_lo = g_hbf[t & 1][1];

        // issue both sub-chunk loads (this group's K-half only)
#pragma unroll
        for (int sub = 0; sub < 2; sub++) {
#pragma unroll
            for (int sp = 0; sp < 2; sp++) {
                const __nv_bfloat16* src = sp ? hin_lo : hin_hi;
                __nv_bfloat16* dst = dsm + ((ks * 2 + sub) * 2 + sp) * 32 * PIT;
#pragma unroll
                for (int q = 0; q < 8; q++) {
                    int u = gtid + q * 128;
                    int row = u >> 5;
                    int c8 = (u & 31) * 8;
                    cp_async16(dst + row * PIT + c8,
                               src + (size_t)(bb + row) * H_ + kbase + sub * 256 + c8);
                }
            }
            cp_commit();
        }

        float c1[2][4] = {0}, c2[2][4] = {0}, c3[2][4] = {0};

        auto do_group = [&](int g) {
            const int sub = g >> 3;
            const int cb = (g & 7) * 32;
            const __nv_bfloat16* ph = dsm + ((ks * 2 + sub) * 2 + 0) * 32 * PIT;
            const __nv_bfloat16* pl = dsm + ((ks * 2 + sub) * 2 + 1) * 32 * PIT;
            uint32_t ah[2][2][4], al[2][2][4];
#pragma unroll
            for (int fm = 0; fm < 2; fm++)
#pragma unroll
                for (int kh = 0; kh < 2; kh++) {
                    ldsm_x4(ah[fm][kh][0], ah[fm][kh][1], ah[fm][kh][2], ah[fm][kh][3],
                            sptr(ph + (a_row + fm * 16) * PIT + cb + kh * 16 + a_koff));
                    ldsm_x4(al[fm][kh][0], al[fm][kh][1], al[fm][kh][2], al[fm][kh][3],
                            sptr(pl + (a_row + fm * 16) * PIT + cb + kh * 16 + a_koff));
                }
#pragma unroll
            for (int fm = 0; fm < 2; fm++)
#pragma unroll
                for (int kh = 0; kh < 2; kh++) {
                    mma_bf16(c1[fm][0], c1[fm][1], c1[fm][2], c1[fm][3],
                             ah[fm][kh][0], ah[fm][kh][1], ah[fm][kh][2], ah[fm][kh][3],
                             bfh[g][kh * 2], bfh[g][kh * 2 + 1]);
                    mma_bf16(c2[fm][0], c2[fm][1], c2[fm][2], c2[fm][3],
                             ah[fm][kh][0], ah[fm][kh][1], ah[fm][kh][2], ah[fm][kh][3],
                             bfl[g][kh * 2], bfl[g][kh * 2 + 1]);
                    mma_bf16(c3[fm][0], c3[fm][1], c3[fm][2], c3[fm][3],
                             al[fm][kh][0], al[fm][kh][1], al[fm][kh][2], al[fm][kh][3],
                             bfh[g][kh * 2], bfh[g][kh * 2 + 1]);
                }
        };

        cp_wait<1>();
        groupbar(ks);
#pragma unroll
        for (int g = 0; g < 8; g++) do_group(g);
        cp_wait<0>();
        groupbar(ks);
#pragma unroll
        for (int g = 8; g < 16; g++) do_group(g);

        // scatter partial sums to SMEM red[ks]
        float* rb = red + ks * 32 * REDP;
#pragma unroll
        for (int fm = 0; fm < 2; fm++) {
            float s0 = c1[fm][0] + c2[fm][0] + c3[fm][0];
            float s1 = c1[fm][1] + c2[fm][1] + c3[fm][1];
            float s2 = c1[fm][2] + c2[fm][2] + c3[fm][2];
            float s3 = c1[fm][3] + c2[fm][3] + c3[fm][3];
            rb[(fm * 16 + srow) * REDP + scol]     = s0;
            rb[(fm * 16 + srow) * REDP + scol + 1] = s1;
            rb[(fm * 16 + 8 + srow) * REDP + scol]     = s2;
            rb[(fm * 16 + 8 + srow) * REDP + scol + 1] = s3;
        }
        __syncthreads();

        // cooperative epilogue: 4 outputs per thread
        {
            const float* r0 = red + erow * REDP + ecol;
            const float* r1 = red + 32 * REDP + erow * REDP + ecol;
            float z0 = tanhf(r0[0] + r1[0] + xv.x);
            float z1 = tanhf(r0[1] + r1[1] + xv.y);
            float z2 = tanhf(r0[2] + r1[2] + xv.z);
            float z3 = tanhf(r0[3] + r1[3] + xv.w);

            if (t < S_ - 1) {
                __nv_bfloat16 h0, l0, h1, l1, h2, l2, h3, l3;
                split2(z0, h0, l0); split2(z1, h1, l1);
                split2(z2, h2, l2); split2(z3, h3, l3);
                __nv_bfloat162 p01, p23;
                uint2 u;
                p01.x = h0; p01.y = h1; p23.x = h2; p23.y = h3;
                u.x = *(uint32_t*)&p01; u.y = *(uint32_t*)&p23;
                *(uint2*)(g_hbf[(t + 1) & 1][0] + (size_t)(bb + erow) * H_ + jb + ecol) = u;
                p01.x = l0; p01.y = l1; p23.x = l2; p23.y = l3;
                u.x = *(uint32_t*)&p01; u.y = *(uint32_t*)&p23;
                *(uint2*)(g_hbf[(t + 1) & 1][1] + (size_t)(bb + erow) * H_ + jb + ecol) = u;
            } else {
                *(float4*)(g_hf + (size_t)(bb + erow) * H_ + jb + ecol) =
                    make_float4(z0, z1, z2, z3);
            }
        }
        __syncthreads();
        if (tid == 0 && t < S_ - 1) bar_arrive(bar);
    }
}

// ---------------------------------------------------------------------------
// Final projection (fp32 SIMT, tiny)
// ---------------------------------------------------------------------------
#define KC   64
#define SROW (KC + 4)

__global__ __launch_bounds__(256) void k_final(const float* __restrict__ Wp,
                                               const float* __restrict__ bp,
                                               float* __restrict__ out) {
    __shared__ float hs[2][32][SROW];
    __shared__ float ws[2][32][SROW];
    const int tid = threadIdx.x;
    const int jb = blockIdx.x * 32;
    const int bb = blockIdx.y * 32;
    const float* __restrict__ hin = g_hf;

    const int r0 = tid >> 4;
    const int c0 = (tid & 15) << 2;

    float4 acc00 = {0,0,0,0}, acc01 = {0,0,0,0}, acc10 = {0,0,0,0}, acc11 = {0,0,0,0};
    const int b0 = (tid >> 4) << 1;
    const int j0 = tid & 15;

    {
#pragma unroll
        for (int q = 0; q < 2; q++) {
            int row = r0 + q * 16;
            cp_async16(&hs[0][row][c0], hin + (size_t)(bb + row) * H_ + c0);
            cp_async16(&ws[0][row][c0], Wp  + (size_t)(jb + row) * H_ + c0);
        }
        cp_commit();
    }

    for (int c = 0; c < H_ / KC; c++) {
        if (c + 1 < H_ / KC) {
            int k0 = (c + 1) * KC;
            int nb = (c + 1) & 1;
#pragma unroll
            for (int q = 0; q < 2; q++) {
                int row = r0 + q * 16;
                cp_async16(&hs[nb][row][c0], hin + (size_t)(bb + row) * H_ + k0 + c0);
                cp_async16(&ws[nb][row][c0], Wp  + (size_t)(jb + row) * H_ + k0 + c0);
            }
            cp_commit();
            cp_wait<1>();
        } else {
            cp_wait<0>();
        }
        __syncthreads();
        const int buf = c & 1;
#pragma unroll
        for (int k4 = 0; k4 < KC; k4 += 4) {
            float4 a0 = *(const float4*)&hs[buf][b0    ][k4];
            float4 a1 = *(const float4*)&hs[buf][b0 + 1][k4];
            float4 w0 = *(const float4*)&ws[buf][j0     ][k4];
            float4 w1 = *(const float4*)&ws[buf][j0 + 16][k4];
            fma4(acc00, a0, w0); fma4(acc01, a0, w1);
            fma4(acc10, a1, w0); fma4(acc11, a1, w1);
        }
        __syncthreads();
    }

    {
        int bg = bb + b0, jg = jb + j0;
        float z;
        z = (acc00.x + acc00.y) + (acc00.z + acc00.w) + bp[jg];
        out[(size_t)bg * O_ + jg] = z;
        z = (acc01.x + acc01.y) + (acc01.z + acc01.w) + bp[jg + 16];
        out[(size_t)bg * O_ + jg + 16] = z;
        z = (acc10.x + acc10.y) + (acc10.z + acc10.w) + bp[jg];
        out[(size_t)(bg + 1) * O_ + jg] = z;
        z = (acc11.x + acc11.y) + (acc11.z + acc11.w) + bp[jg + 16];
        out[(size_t)(bg + 1) * O_ + jg + 16] = z;
    }
}

// ---------------------------------------------------------------------------
// launch
// ---------------------------------------------------------------------------
extern "C" void kernel_launch(void* const* d_in, const int* in_sizes, int n_in,
                              void* d_out, int out_size) {
    const float* x  = (const float*)d_in[0];
    const float* Wx = (const float*)d_in[1];
    const float* bx = (const float*)d_in[2];
    const float* Wh = (const float*)d_in[3];
    const float* Wp = (const float*)d_in[4];
    const float* bp = (const float*)d_in[5];
    float* out = (float*)d_out;

    const int XSMEM = (2 * 2 * 128 * XPA + 2 * 2 * 64 * XPA) * (int)sizeof(__nv_bfloat16);
    const int RSMEM = 8 * 32 * PIT * (int)sizeof(__nv_bfloat16)
                    + 2 * 32 * REDP * (int)sizeof(float);
    cudaFuncSetAttribute(k_xproj_mma, cudaFuncAttributeMaxDynamicSharedMemorySize, XSMEM);
    cudaFuncSetAttribute(k_rnn, cudaFuncAttributeMaxDynamicSharedMemorySize, RSMEM);

    k_convert_x<<<(S_ * B_ * I_ / 4) / 256, 256>>>(x);
    k_convert_wx<<<(H_ * I_ / 4) / 256, 256>>>(Wx);
    k_xproj_mma<<<dim3(H_ / 64, (B_ * S_) / 128), 256, XSMEM>>>(bx);
    k_rnn<<<NCTA, 256, RSMEM>>>(Wh);
    k_final<<<dim3(O_ / 32, B_ / 32), 256>>>(Wp, bp, out);
}

// round 7
// speedup vs baseline: 3.6290x; 1.0459x over previous
#include <cuda_runtime.h>
#include <cuda_bf16.h>
#include <math.h>
#include <stdint.h>

#define B_   128
#define S_   512
#define I_   512
#define H_   1024
#define O_   512
#define NCTA 128

// ---------------------------------------------------------------------------
// device globals (allocation-free scratch)
// ---------------------------------------------------------------------------
__device__ __align__(256) float g_xproj[(size_t)S_ * B_ * H_];        // [m=s*B+b][h]
__device__ __align__(256) float g_hf[B_ * H_];                        // fp32 final h
__device__ __align__(256) __nv_bfloat16 g_hbf[2][2][B_ * H_];         // [pingpong][hi/lo][b][k]
__device__ __align__(256) __nv_bfloat16 g_xr[2][(size_t)S_ * B_ * I_];// [hi/lo][m=s*B+b][i]
__device__ __align__(256) __nv_bfloat16 g_Wxbf[2][(size_t)H_ * I_];   // [hi/lo][h][i]
__device__ unsigned g_gbar[4];                                        // per-bt-group barrier

// ---------------------------------------------------------------------------
// helpers
// ---------------------------------------------------------------------------
__device__ __forceinline__ void cp_async16(void* s, const void* g) {
    uint32_t sa = (uint32_t)__cvta_generic_to_shared(s);
    asm volatile("cp.async.cg.shared.global [%0], [%1], 16;" :: "r"(sa), "l"(g));
}
__device__ __forceinline__ void cp_commit() { asm volatile("cp.async.commit_group;"); }
template <int N> __device__ __forceinline__ void cp_wait() {
    asm volatile("cp.async.wait_group %0;" :: "n"(N));
}
__device__ __forceinline__ uint32_t sptr(const void* p) {
    return (uint32_t)__cvta_generic_to_shared(p);
}
__device__ __forceinline__ void ldsm_x4(uint32_t& r0, uint32_t& r1, uint32_t& r2, uint32_t& r3,
                                        uint32_t addr) {
    asm volatile("ldmatrix.sync.aligned.m8n8.x4.shared.b16 {%0,%1,%2,%3}, [%4];"
                 : "=r"(r0), "=r"(r1), "=r"(r2), "=r"(r3) : "r"(addr));
}
__device__ __forceinline__ void mma_bf16(float& c0, float& c1, float& c2, float& c3,
                                         uint32_t a0, uint32_t a1, uint32_t a2, uint32_t a3,
                                         uint32_t b0, uint32_t b1) {
    asm volatile("mma.sync.aligned.m16n8k16.row.col.f32.bf16.bf16.f32 "
                 "{%0,%1,%2,%3}, {%4,%5,%6,%7}, {%8,%9}, {%0,%1,%2,%3};"
                 : "+f"(c0), "+f"(c1), "+f"(c2), "+f"(c3)
                 : "r"(a0), "r"(a1), "r"(a2), "r"(a3), "r"(b0), "r"(b1));
}
__device__ __forceinline__ void fma4(float4& acc, const float4 a, const float4 b) {
    acc.x = fmaf(a.x, b.x, acc.x);
    acc.y = fmaf(a.y, b.y, acc.y);
    acc.z = fmaf(a.z, b.z, acc.z);
    acc.w = fmaf(a.w, b.w, acc.w);
}
__device__ __forceinline__ void split2(float v, __nv_bfloat16& hi, __nv_bfloat16& lo) {
    hi = __float2bfloat16(v);
    lo = __float2bfloat16(v - __bfloat162float(hi));
}
__device__ __forceinline__ void bar_arrive(unsigned* p) {
    asm volatile("red.release.gpu.global.add.u32 [%0], 1;" :: "l"(p) : "memory");
}
__device__ __forceinline__ void bar_wait(unsigned* p, unsigned target) {
    unsigned v;
    do {
        asm volatile("ld.acquire.gpu.global.u32 %0, [%1];" : "=r"(v) : "l"(p) : "memory");
    } while ((int)(v - target) < 0);
}
__device__ __forceinline__ uint32_t cl_rank() {
    uint32_t r;
    asm("mov.u32 %0, %%cluster_ctarank;" : "=r"(r));
    return r;
}
#define MBAR_INIT(mbar, cnt) \
    asm volatile("mbarrier.init.shared.b64 [%0], %1;" :: "r"(mbar), "r"(cnt) : "memory")
#define MBAR_EXPECT(mbar, tx) \
    asm volatile("mbarrier.arrive.expect_tx.shared.b64 _, [%0], %1;" :: "r"(mbar), "r"(tx) : "memory")
#define MBAR_WAIT(mbar, ph) do {                                              \
    uint32_t _done = 0;                                                       \
    while (!_done) {                                                          \
        asm volatile("{\n\t.reg .pred p;\n\t"                                 \
                     "mbarrier.try_wait.parity.acquire.cta.shared::cta.b64 p, [%1], %2;\n\t" \
                     "selp.b32 %0, 1, 0, p;\n\t}"                             \
                     : "=r"(_done) : "r"(mbar), "r"(ph) : "memory");          \
    }                                                                         \
} while (0)
#define BULK_MC(dst, src, bytes, mbar, mask) \
    asm volatile("cp.async.bulk.shared::cluster.global.mbarrier::complete_tx::bytes.multicast::cluster " \
                 "[%0], [%1], %2, [%3], %4;" \
                 :: "r"(dst), "l"(src), "r"(bytes), "r"(mbar), "h"((uint16_t)(mask)) : "memory")
#define CLUSTER_SYNC_() do { \
    asm volatile("barrier.cluster.arrive.aligned;" ::: "memory"); \
    asm volatile("barrier.cluster.wait.aligned;" ::: "memory"); \
} while (0)

// ---------------------------------------------------------------------------
// conversions: x -> reordered hi/lo bf16 [m=s*B+b][i]; Wx -> hi/lo
// ---------------------------------------------------------------------------
__global__ __launch_bounds__(256) void k_convert_x(const float* __restrict__ x) {
    int gid = blockIdx.x * blockDim.x + threadIdx.x;   // S*B*I/4 units
    if (gid < 4) g_gbar[gid] = 0;                      // reset barriers each launch
    int i4 = (gid & (I_ / 4 - 1)) * 4;
    int m  = gid >> 7;                                 // I_/4 = 128
    int s = m / B_, b = m % B_;
    float4 v = *(const float4*)(x + ((size_t)b * S_ + s) * I_ + i4);
    __nv_bfloat16 h0, l0, h1, l1, h2, l2, h3, l3;
    split2(v.x, h0, l0); split2(v.y, h1, l1);
    split2(v.z, h2, l2); split2(v.w, h3, l3);
    __nv_bfloat162 p;
    __nv_bfloat16* dh = g_xr[0] + (size_t)m * I_ + i4;
    __nv_bfloat16* dl = g_xr[1] + (size_t)m * I_ + i4;
    p.x = h0; p.y = h1; *(__nv_bfloat162*)(dh)     = p;
    p.x = h2; p.y = h3; *(__nv_bfloat162*)(dh + 2) = p;
    p.x = l0; p.y = l1; *(__nv_bfloat162*)(dl)     = p;
    p.x = l2; p.y = l3; *(__nv_bfloat162*)(dl + 2) = p;
}

__global__ __launch_bounds__(256) void k_convert_wx(const float* __restrict__ Wx) {
    int gid = blockIdx.x * blockDim.x + threadIdx.x;   // H*I/4 units
    int i = gid * 4;
    float4 v = *(const float4*)(Wx + i);
    __nv_bfloat16 h0, l0, h1, l1, h2, l2, h3, l3;
    split2(v.x, h0, l0); split2(v.y, h1, l1);
    split2(v.z, h2, l2); split2(v.w, h3, l3);
    __nv_bfloat162 p;
    p.x = h0; p.y = h1; *(__nv_bfloat162*)(g_Wxbf[0] + i)     = p;
    p.x = h2; p.y = h3; *(__nv_bfloat162*)(g_Wxbf[0] + i + 2) = p;
    p.x = l0; p.y = l1; *(__nv_bfloat162*)(g_Wxbf[1] + i)     = p;
    p.x = l2; p.y = l3; *(__nv_bfloat162*)(g_Wxbf[1] + i + 2) = p;
}

// ---------------------------------------------------------------------------
// xproj GEMM via bf16x2-split mma (unchanged)
// ---------------------------------------------------------------------------
#define XKC  64
#define XPA  72

__global__ __launch_bounds__(256) void k_xproj_mma(const float* __restrict__ bx) {
    extern __shared__ __nv_bfloat16 dsm[];
    __nv_bfloat16* sa = dsm;
    __nv_bfloat16* sb = dsm + 2 * 2 * 128 * XPA;

    const int tid = threadIdx.x;
    const int lane = tid & 31, wid = tid >> 5;
    const int n0 = blockIdx.x * 64;
    const int m0 = blockIdx.y * 128;
    const int wm = (wid & 3) * 32;
    const int wn = (wid >> 2) * 32;

    float acc[2][4][4];
#pragma unroll
    for (int a = 0; a < 2; a++)
#pragma unroll
        for (int b = 0; b < 4; b++)
#pragma unroll
            for (int c = 0; c < 4; c++) acc[a][b][c] = 0.0f;

    auto load_chunk = [&](int buf, int k0) {
#pragma unroll
        for (int sp = 0; sp < 2; sp++) {
            __nv_bfloat16* da = sa + (size_t)(buf * 2 + sp) * 128 * XPA;
            const __nv_bfloat16* ga = g_xr[sp];
#pragma unroll
            for (int q = 0; q < 4; q++) {
                int u = tid + q * 256;
                int row = u >> 3, c16 = (u & 7) * 8;
                cp_async16(da + row * XPA + c16,
                           ga + (size_t)(m0 + row) * I_ + k0 + c16);
            }
            __nv_bfloat16* db = sb + (size_t)(buf * 2 + sp) * 64 * XPA;
            const __nv_bfloat16* gb = g_Wxbf[sp];
#pragma unroll
            for (int q = 0; q < 2; q++) {
                int u = tid + q * 256;
                int row = u >> 3, c16 = (u & 7) * 8;
                cp_async16(db + row * XPA + c16,
                           gb + (size_t)(n0 + row) * I_ + k0 + c16);
            }
        }
        cp_commit();
    };

    load_chunk(0, 0);

    const int a_row  = wm + (lane & 15);
    const int a_koff = (lane >> 4) * 8;
    const int b_row  = wn + ((lane >> 4) * 8) + (lane & 7);
    const int b_koff = ((lane >> 3) & 1) * 8;

    for (int ch = 0; ch < I_ / XKC; ch++) {
        if (ch + 1 < I_ / XKC) { load_chunk((ch + 1) & 1, (ch + 1) * XKC); cp_wait<1>(); }
        else                   { cp_wait<0>(); }
        __syncthreads();
        const int buf = ch & 1;
        const __nv_bfloat16* ah_base = sa + (size_t)(buf * 2 + 0) * 128 * XPA;
        const __nv_bfloat16* al_base = sa + (size_t)(buf * 2 + 1) * 128 * XPA;
        const __nv_bfloat16* bh_base = sb + (size_t)(buf * 2 + 0) * 64 * XPA;
        const __nv_bfloat16* bl_base = sb + (size_t)(buf * 2 + 1) * 64 * XPA;
#pragma unroll
        for (int kk = 0; kk < XKC; kk += 16) {
            uint32_t ah[2][4], al[2][4];
#pragma unroll
            for (int fm = 0; fm < 2; fm++) {
                ldsm_x4(ah[fm][0], ah[fm][1], ah[fm][2], ah[fm][3],
                        sptr(ah_base + (a_row + fm * 16) * XPA + kk + a_koff));
                ldsm_x4(al[fm][0], al[fm][1], al[fm][2], al[fm][3],
                        sptr(al_base + (a_row + fm * 16) * XPA + kk + a_koff));
            }
            uint32_t bh[2][4], bl[2][4];
#pragma unroll
            for (int g = 0; g < 2; g++) {
                ldsm_x4(bh[g][0], bh[g][1], bh[g][2], bh[g][3],
                        sptr(bh_base + (b_row + g * 16) * XPA + kk + b_koff));
                ldsm_x4(bl[g][0], bl[g][1], bl[g][2], bl[g][3],
                        sptr(bl_base + (b_row + g * 16) * XPA + kk + b_koff));
            }
#pragma unroll
            for (int fm = 0; fm < 2; fm++)
#pragma unroll
                for (int fn = 0; fn < 4; fn++) {
                    int g = fn >> 1, o = (fn & 1) * 2;
                    float* c = acc[fm][fn];
                    mma_bf16(c[0], c[1], c[2], c[3],
                             ah[fm][0], ah[fm][1], ah[fm][2], ah[fm][3],
                             bh[g][o], bh[g][o + 1]);
                    mma_bf16(c[0], c[1], c[2], c[3],
                             ah[fm][0], ah[fm][1], ah[fm][2], ah[fm][3],
                             bl[g][o], bl[g][o + 1]);
                    mma_bf16(c[0], c[1], c[2], c[3],
                             al[fm][0], al[fm][1], al[fm][2], al[fm][3],
                             bh[g][o], bh[g][o + 1]);
                }
        }
        __syncthreads();
    }

    const int r = lane >> 2;
    const int cp = (lane & 3) * 2;
#pragma unroll
    for (int fn = 0; fn < 4; fn++) {
        int col = n0 + wn + fn * 8 + cp;
        float2 bias = *(const float2*)(bx + col);
#pragma unroll
        for (int fm = 0; fm < 2; fm++) {
            int mr = m0 + wm + fm * 16 + r;
            float2 v0 = make_float2(acc[fm][fn][0] + bias.x, acc[fm][fn][1] + bias.y);
            float2 v1 = make_float2(acc[fm][fn][2] + bias.x, acc[fm][fn][3] + bias.y);
            *(float2*)(g_xproj + (size_t)mr * H_ + col) = v0;
            *(float2*)(g_xproj + (size_t)(mr + 8) * H_ + col) = v1;
        }
    }
}

// ---------------------------------------------------------------------------
// Persistent recurrence kernel v4: cluster-4 multicast h exchange.
// 128 CTAs = 32 clusters of 4 (same bt, consecutive jt). 256 thr =
// 4 n-warps x 2 K-half groups. Wh frags register-resident.
// h tile (identical across cluster) delivered by multicast bulk copies.
// ---------------------------------------------------------------------------
#define PIT  264   // halves per SMEM row (256 + 8), 528B pitch
#define REDP 33    // red row pitch (floats)
#define PLANE_BYTES (32 * PIT * 2)
#define SMEM_PLANES (8 * 32 * PIT)                     // halves
#define RED_OFF_B   (SMEM_PLANES * 2)                  // bytes
#define MBAR_OFF_B  (RED_OFF_B + 2 * 32 * REDP * 4)    // bytes (8-aligned)

__global__ __launch_bounds__(256, 1) __cluster_dims__(4, 1, 1)
void k_rnn(const float* __restrict__ Wh) {
    extern __shared__ __nv_bfloat16 dsm[];
    float* red = (float*)((char*)dsm + RED_OFF_B);     // [2][32][REDP]
    uint32_t mb0 = sptr((char*)dsm + MBAR_OFF_B);      // 4 mbarriers: [ks][sub]

    const int tid = threadIdx.x;
    const int lane = tid & 31, wid = tid >> 5;
    const int ks = wid >> 2;          // K-half group
    const int nw = wid & 3;           // n-warp (8 j-cols)
    const int gtid = tid & 127;
    const int jt = blockIdx.x & 31, bt = blockIdx.x >> 5;
    const int jb = jt * 32, bb = bt * 32;
    const uint32_t rank = cl_rank();
    unsigned* bar = &g_gbar[bt];

    // init mbarriers (arrive count 1 = the expect_tx arrival)
    if (tid == 0) {
#pragma unroll
        for (int i = 0; i < 4; i++) MBAR_INIT(mb0 + i * 8, 1);
    }
    __syncthreads();
    CLUSTER_SYNC_();   // peers' barriers live before any multicast targets them

    // --- stage this group's Wh K-half into SMEM planes (split hi/lo) ---
    {
        const int kbase = ks * 512;
#pragma unroll
        for (int sub = 0; sub < 2; sub++) {
            __nv_bfloat16* dh = dsm + ((ks * 2 + sub) * 2 + 0) * 32 * PIT;
            __nv_bfloat16* dl = dsm + ((ks * 2 + sub) * 2 + 1) * 32 * PIT;
#pragma unroll
            for (int q = 0; q < 16; q++) {
                int u = gtid + q * 128;
                int row = u >> 6;
                int c4 = (u & 63) * 4;
                float4 v = *(const float4*)(Wh + (size_t)(jb + row) * H_ + kbase + sub * 256 + c4);
                __nv_bfloat16 h0, l0, h1, l1, h2, l2, h3, l3;
                split2(v.x, h0, l0); split2(v.y, h1, l1);
                split2(v.z, h2, l2); split2(v.w, h3, l3);
                __nv_bfloat16* ph = dh + row * PIT + c4;
                __nv_bfloat16* pl = dl + row * PIT + c4;
                ph[0] = h0; ph[1] = h1; ph[2] = h2; ph[3] = h3;
                pl[0] = l0; pl[1] = l1; pl[2] = l2; pl[3] = l3;
            }
        }
    }
    __syncthreads();

    // --- register-resident Wh fragments (n8 x K512 per warp) ---
    const int b_row  = nw * 8 + (lane & 7);
    const int b_koff = (lane >> 3) * 8;
    uint32_t bfh[16][4], bfl[16][4];
#pragma unroll
    for (int g = 0; g < 16; g++) {
        int sub = g >> 3, col = (g & 7) * 32 + b_koff;
        const __nv_bfloat16* ph = dsm + ((ks * 2 + sub) * 2 + 0) * 32 * PIT;
        const __nv_bfloat16* pl = dsm + ((ks * 2 + sub) * 2 + 1) * 32 * PIT;
        ldsm_x4(bfh[g][0], bfh[g][1], bfh[g][2], bfh[g][3], sptr(ph + b_row * PIT + col));
        ldsm_x4(bfl[g][0], bfl[g][1], bfl[g][2], bfl[g][3], sptr(pl + b_row * PIT + col));
    }
    __syncthreads();

    // epilogue mapping (all 256 threads, 4 outputs each)
    const int erow = tid >> 3;
    const int ecol = (tid & 7) * 4;

    // --- t = 0: h(1) = tanh(xproj[0]) ---
    {
        float4 v = *(const float4*)(g_xproj + (size_t)(bb + erow) * H_ + jb + ecol);
        float t0 = tanhf(v.x), t1 = tanhf(v.y), t2 = tanhf(v.z), t3 = tanhf(v.w);
        __nv_bfloat16 h0, l0, h1, l1, h2, l2, h3, l3;
        split2(t0, h0, l0); split2(t1, h1, l1);
        split2(t2, h2, l2); split2(t3, h3, l3);
        __nv_bfloat162 p01, p23;
        uint2 u;
        p01.x = h0; p01.y = h1; p23.x = h2; p23.y = h3;
        u.x = *(uint32_t*)&p01; u.y = *(uint32_t*)&p23;
        *(uint2*)(g_hbf[1][0] + (size_t)(bb + erow) * H_ + jb + ecol) = u;
        p01.x = l0; p01.y = l1; p23.x = l2; p23.y = l3;
        u.x = *(uint32_t*)&p01; u.y = *(uint32_t*)&p23;
        *(uint2*)(g_hbf[1][1] + (size_t)(bb + erow) * H_ + jb + ecol) = u;
    }
    __syncthreads();
    if (tid == 0) bar_arrive(bar);

    const int a_row  = lane & 15;
    const int a_koff = (lane >> 4) * 8;
    const int srow = lane >> 2;
    const int scol = nw * 8 + (lane & 3) * 2;

    // copy-issue role: warp wid handles plane wid, rows [rank*8, rank*8+8)
    const int ip  = wid;                 // plane 0..7
    const int isp  = ip & 1;             // split (hi/lo)
    const int isub = (ip >> 1) & 1;      // sub-chunk
    const int iks  = ip >> 2;            // K-half
    const uint32_t idst0 = sptr((char*)dsm + (size_t)ip * PLANE_BYTES) + rank * 8 * PIT * 2;
    const uint32_t imbar = mb0 + (iks * 2 + isub) * 8;

    for (int t = 1; t < S_; t++) {
        // independent prefetch fills the barrier-wait shadow
        const float* xp = g_xproj + (size_t)t * B_ * H_;
        float4 xv = __ldg((const float4*)(xp + (size_t)(bb + erow) * H_ + jb + ecol));

        if (tid == 0) {
            bar_wait(bar, 32u * (unsigned)t);
#pragma unroll
            for (int i = 0; i < 4; i++) MBAR_EXPECT(mb0 + i * 8, 32768u);
        }
        __syncthreads();

        // multicast bulk copies: each CTA ships its 8-row slice of every plane
        if (lane == 0) {
            const __nv_bfloat16* src = g_hbf[t & 1][isp];
            const size_t base = (size_t)(bb + rank * 8) * H_ + iks * 512 + isub * 256;
#pragma unroll
            for (int rrow = 0; rrow < 8; rrow++) {
                BULK_MC(idst0 + rrow * PIT * 2,
                        src + base + (size_t)rrow * H_,
                        512u, imbar, 0xFu);
            }
        }

        float c1[2][4] = {0}, c2[2][4] = {0}, c3[2][4] = {0};

        auto do_group = [&](int g) {
            const int sub = g >> 3;
            const int cb = (g & 7) * 32;
            const __nv_bfloat16* ph = dsm + ((ks * 2 + sub) * 2 + 0) * 32 * PIT;
            const __nv_bfloat16* pl = dsm + ((ks * 2 + sub) * 2 + 1) * 32 * PIT;
            uint32_t ah[2][2][4], al[2][2][4];
#pragma unroll
            for (int fm = 0; fm < 2; fm++)
#pragma unroll
                for (int kh = 0; kh < 2; kh++) {
                    ldsm_x4(ah[fm][kh][0], ah[fm][kh][1], ah[fm][kh][2], ah[fm][kh][3],
                            sptr(ph + (a_row + fm * 16) * PIT + cb + kh * 16 + a_koff));
                    ldsm_x4(al[fm][kh][0], al[fm][kh][1], al[fm][kh][2], al[fm][kh][3],
                            sptr(pl + (a_row + fm * 16) * PIT + cb + kh * 16 + a_koff));
                }
#pragma unroll
            for (int fm = 0; fm < 2; fm++)
#pragma unroll
                for (int kh = 0; kh < 2; kh++) {
                    mma_bf16(c1[fm][0], c1[fm][1], c1[fm][2], c1[fm][3],
                             ah[fm][kh][0], ah[fm][kh][1], ah[fm][kh][2], ah[fm][kh][3],
                             bfh[g][kh * 2], bfh[g][kh * 2 + 1]);
                    mma_bf16(c2[fm][0], c2[fm][1], c2[fm][2], c2[fm][3],
                             ah[fm][kh][0], ah[fm][kh][1], ah[fm][kh][2], ah[fm][kh][3],
                             bfl[g][kh * 2], bfl[g][kh * 2 + 1]);
                    mma_bf16(c3[fm][0], c3[fm][1], c3[fm][2], c3[fm][3],
                             al[fm][kh][0], al[fm][kh][1], al[fm][kh][2], al[fm][kh][3],
                             bfh[g][kh * 2], bfh[g][kh * 2 + 1]);
                }
        };

        const uint32_t ph_par = (unsigned)(t - 1) & 1u;
        MBAR_WAIT(mb0 + (ks * 2 + 0) * 8, ph_par);
#pragma unroll
        for (int g = 0; g < 8; g++) do_group(g);
        MBAR_WAIT(mb0 + (ks * 2 + 1) * 8, ph_par);
#pragma unroll
        for (int g = 8; g < 16; g++) do_group(g);

        // scatter partial sums to SMEM red[ks]
        float* rb = red + ks * 32 * REDP;
#pragma unroll
        for (int fm = 0; fm < 2; fm++) {
            float s0 = c1[fm][0] + c2[fm][0] + c3[fm][0];
            float s1 = c1[fm][1] + c2[fm][1] + c3[fm][1];
            float s2 = c1[fm][2] + c2[fm][2] + c3[fm][2];
            float s3 = c1[fm][3] + c2[fm][3] + c3[fm][3];
            rb[(fm * 16 + srow) * REDP + scol]     = s0;
            rb[(fm * 16 + srow) * REDP + scol + 1] = s1;
            rb[(fm * 16 + 8 + srow) * REDP + scol]     = s2;
            rb[(fm * 16 + 8 + srow) * REDP + scol + 1] = s3;
        }
        __syncthreads();

        // cooperative epilogue: 4 outputs per thread
        {
            const float* r0 = red + erow * REDP + ecol;
            const float* r1 = red + 32 * REDP + erow * REDP + ecol;
            float z0 = tanhf(r0[0] + r1[0] + xv.x);
            float z1 = tanhf(r0[1] + r1[1] + xv.y);
            float z2 = tanhf(r0[2] + r1[2] + xv.z);
            float z3 = tanhf(r0[3] + r1[3] + xv.w);

            if (t < S_ - 1) {
                __nv_bfloat16 h0, l0, h1, l1, h2, l2, h3, l3;
                split2(z0, h0, l0); split2(z1, h1, l1);
                split2(z2, h2, l2); split2(z3, h3, l3);
                __nv_bfloat162 p01, p23;
                uint2 u;
                p01.x = h0; p01.y = h1; p23.x = h2; p23.y = h3;
                u.x = *(uint32_t*)&p01; u.y = *(uint32_t*)&p23;
                *(uint2*)(g_hbf[(t + 1) & 1][0] + (size_t)(bb + erow) * H_ + jb + ecol) = u;
                p01.x = l0; p01.y = l1; p23.x = l2; p23.y = l3;
                u.x = *(uint32_t*)&p01; u.y = *(uint32_t*)&p23;
                *(uint2*)(g_hbf[(t + 1) & 1][1] + (size_t)(bb + erow) * H_ + jb + ecol) = u;
            } else {
                *(float4*)(g_hf + (size_t)(bb + erow) * H_ + jb + ecol) =
                    make_float4(z0, z1, z2, z3);
            }
        }
        __syncthreads();
        if (tid == 0 && t < S_ - 1) bar_arrive(bar);
    }
    CLUSTER_SYNC_();   // no CTA exits while peers' multicasts may target it
}

// ---------------------------------------------------------------------------
// Final projection (fp32 SIMT, tiny)
// ---------------------------------------------------------------------------
#define KC   64
#define SROW (KC + 4)

__global__ __launch_bounds__(256) void k_final(const float* __restrict__ Wp,
                                               const float* __restrict__ bp,
                                               float* __restrict__ out) {
    __shared__ float hs[2][32][SROW];
    __shared__ float ws[2][32][SROW];
    const int tid = threadIdx.x;
    const int jb = blockIdx.x * 32;
    const int bb = blockIdx.y * 32;
    const float* __restrict__ hin = g_hf;

    const int r0 = tid >> 4;
    const int c0 = (tid & 15) << 2;

    float4 acc00 = {0,0,0,0}, acc01 = {0,0,0,0}, acc10 = {0,0,0,0}, acc11 = {0,0,0,0};
    const int b0 = (tid >> 4) << 1;
    const int j0 = tid & 15;

    {
#pragma unroll
        for (int q = 0; q < 2; q++) {
            int row = r0 + q * 16;
            cp_async16(&hs[0][row][c0], hin + (size_t)(bb + row) * H_ + c0);
            cp_async16(&ws[0][row][c0], Wp  + (size_t)(jb + row) * H_ + c0);
        }
        cp_commit();
    }

    for (int c = 0; c < H_ / KC; c++) {
        if (c + 1 < H_ / KC) {
            int k0 = (c + 1) * KC;
            int nb = (c + 1) & 1;
#pragma unroll
            for (int q = 0; q < 2; q++) {
                int row = r0 + q * 16;
                cp_async16(&hs[nb][row][c0], hin + (size_t)(bb + row) * H_ + k0 + c0);
                cp_async16(&ws[nb][row][c0], Wp  + (size_t)(jb + row) * H_ + k0 + c0);
            }
            cp_commit();
            cp_wait<1>();
        } else {
            cp_wait<0>();
        }
        __syncthreads();
        const int buf = c & 1;
#pragma unroll
        for (int k4 = 0; k4 < KC; k4 += 4) {
            float4 a0 = *(const float4*)&hs[buf][b0    ][k4];
            float4 a1 = *(const float4*)&hs[buf][b0 + 1][k4];
            float4 w0 = *(const float4*)&ws[buf][j0     ][k4];
            float4 w1 = *(const float4*)&ws[buf][j0 + 16][k4];
            fma4(acc00, a0, w0); fma4(acc01, a0, w1);
            fma4(acc10, a1, w0); fma4(acc11, a1, w1);
        }
        __syncthreads();
    }

    {
        int bg = bb + b0, jg = jb + j0;
        float z;
        z = (acc00.x + acc00.y) + (acc00.z + acc00.w) + bp[jg];
        out[(size_t)bg * O_ + jg] = z;
        z = (acc01.x + acc01.y) + (acc01.z + acc01.w) + bp[jg + 16];
        out[(size_t)bg * O_ + jg + 16] = z;
        z = (acc10.x + acc10.y) + (acc10.z + acc10.w) + bp[jg];
        out[(size_t)(bg + 1) * O_ + jg] = z;
        z = (acc11.x + acc11.y) + (acc11.z + acc11.w) + bp[jg + 16];
        out[(size_t)(bg + 1) * O_ + jg + 16] = z;
    }
}

// ---------------------------------------------------------------------------
// launch
// ---------------------------------------------------------------------------
extern "C" void kernel_launch(void* const* d_in, const int* in_sizes, int n_in,
                              void* d_out, int out_size) {
    const float* x  = (const float*)d_in[0];
    const float* Wx = (const float*)d_in[1];
    const float* bx = (const float*)d_in[2];
    const float* Wh = (const float*)d_in[3];
    const float* Wp = (const float*)d_in[4];
    const float* bp = (const float*)d_in[5];
    float* out = (float*)d_out;

    const int XSMEM = (2 * 2 * 128 * XPA + 2 * 2 * 64 * XPA) * (int)sizeof(__nv_bfloat16);
    const int RSMEM = MBAR_OFF_B + 4 * 8;
    cudaFuncSetAttribute(k_xproj_mma, cudaFuncAttributeMaxDynamicSharedMemorySize, XSMEM);
    cudaFuncSetAttribute(k_rnn, cudaFuncAttributeMaxDynamicSharedMemorySize, RSMEM);

    k_convert_x<<<(S_ * B_ * I_ / 4) / 256, 256>>>(x);
    k_convert_wx<<<(H_ * I_ / 4) / 256, 256>>>(Wx);
    k_xproj_mma<<<dim3(H_ / 64, (B_ * S_) / 128), 256, XSMEM>>>(bx);
    k_rnn<<<NCTA, 256, RSMEM>>>(Wh);
    k_final<<<dim3(O_ / 32, B_ / 32), 256>>>(Wp, bp, out);
}

// round 8
// speedup vs baseline: 3.8382x; 1.0576x over previous
#include <cuda_runtime.h>
#include <cuda_bf16.h>
#include <math.h>
#include <stdint.h>

#define B_   128
#define S_   512
#define I_   512
#define H_   1024
#define O_   512
#define NCTA 128

// ---------------------------------------------------------------------------
// device globals (allocation-free scratch)
// ---------------------------------------------------------------------------
__device__ __align__(256) float g_xproj[(size_t)S_ * B_ * H_];        // [m=s*B+b][h]
__device__ __align__(256) float g_hf[B_ * H_];                        // fp32 final h
__device__ __align__(256) __nv_bfloat16 g_hbf[2][2][B_ * H_];         // [pingpong][hi/lo][b][k]
__device__ __align__(256) __nv_bfloat16 g_xr[2][(size_t)S_ * B_ * I_];// [hi/lo][m=s*B+b][i]
__device__ __align__(256) __nv_bfloat16 g_Wxbf[2][(size_t)H_ * I_];   // [hi/lo][h][i]
__device__ unsigned g_flag[4][4];   // [bt][kslice]: 8 producer arrivals per step

// ---------------------------------------------------------------------------
// helpers
// ---------------------------------------------------------------------------
__device__ __forceinline__ void cp_async16(void* s, const void* g) {
    uint32_t sa = (uint32_t)__cvta_generic_to_shared(s);
    asm volatile("cp.async.cg.shared.global [%0], [%1], 16;" :: "r"(sa), "l"(g));
}
__device__ __forceinline__ void cp_commit() { asm volatile("cp.async.commit_group;"); }
template <int N> __device__ __forceinline__ void cp_wait() {
    asm volatile("cp.async.wait_group %0;" :: "n"(N));
}
__device__ __forceinline__ uint32_t sptr(const void* p) {
    return (uint32_t)__cvta_generic_to_shared(p);
}
__device__ __forceinline__ void ldsm_x4(uint32_t& r0, uint32_t& r1, uint32_t& r2, uint32_t& r3,
                                        uint32_t addr) {
    asm volatile("ldmatrix.sync.aligned.m8n8.x4.shared.b16 {%0,%1,%2,%3}, [%4];"
                 : "=r"(r0), "=r"(r1), "=r"(r2), "=r"(r3) : "r"(addr));
}
__device__ __forceinline__ void mma_bf16(float& c0, float& c1, float& c2, float& c3,
                                         uint32_t a0, uint32_t a1, uint32_t a2, uint32_t a3,
                                         uint32_t b0, uint32_t b1) {
    asm volatile("mma.sync.aligned.m16n8k16.row.col.f32.bf16.bf16.f32 "
                 "{%0,%1,%2,%3}, {%4,%5,%6,%7}, {%8,%9}, {%0,%1,%2,%3};"
                 : "+f"(c0), "+f"(c1), "+f"(c2), "+f"(c3)
                 : "r"(a0), "r"(a1), "r"(a2), "r"(a3), "r"(b0), "r"(b1));
}
__device__ __forceinline__ void fma4(float4& acc, const float4 a, const float4 b) {
    acc.x = fmaf(a.x, b.x, acc.x);
    acc.y = fmaf(a.y, b.y, acc.y);
    acc.z = fmaf(a.z, b.z, acc.z);
    acc.w = fmaf(a.w, b.w, acc.w);
}
__device__ __forceinline__ void split2(float v, __nv_bfloat16& hi, __nv_bfloat16& lo) {
    hi = __float2bfloat16(v);
    lo = __float2bfloat16(v - __bfloat162float(hi));
}
__device__ __forceinline__ void bar_arrive(unsigned* p) {
    asm volatile("red.release.gpu.global.add.u32 [%0], 1;" :: "l"(p) : "memory");
}
__device__ __forceinline__ void bar_wait(unsigned* p, unsigned target) {
    unsigned v;
    do {
        asm volatile("ld.acquire.gpu.global.u32 %0, [%1];" : "=r"(v) : "l"(p) : "memory");
    } while ((int)(v - target) < 0);
}
__device__ __forceinline__ uint32_t cl_rank() {
    uint32_t r;
    asm("mov.u32 %0, %%cluster_ctarank;" : "=r"(r));
    return r;
}
#define MBAR_INIT(mbar, cnt) \
    asm volatile("mbarrier.init.shared.b64 [%0], %1;" :: "r"(mbar), "r"(cnt) : "memory")
#define MBAR_EXPECT(mbar, tx) \
    asm volatile("mbarrier.arrive.expect_tx.shared.b64 _, [%0], %1;" :: "r"(mbar), "r"(tx) : "memory")
#define MBAR_WAIT(mbar, ph) do {                                              \
    uint32_t _done = 0;                                                       \
    while (!_done) {                                                          \
        asm volatile("{\n\t.reg .pred p;\n\t"                                 \
                     "mbarrier.try_wait.parity.acquire.cta.shared::cta.b64 p, [%1], %2;\n\t" \
                     "selp.b32 %0, 1, 0, p;\n\t}"                             \
                     : "=r"(_done) : "r"(mbar), "r"(ph) : "memory");          \
    }                                                                         \
} while (0)
#define BULK_MC(dst, src, bytes, mbar, mask) \
    asm volatile("cp.async.bulk.shared::cluster.global.mbarrier::complete_tx::bytes.multicast::cluster " \
                 "[%0], [%1], %2, [%3], %4;" \
                 :: "r"(dst), "l"(src), "r"(bytes), "r"(mbar), "h"((uint16_t)(mask)) : "memory")
#define CLUSTER_SYNC_() do { \
    asm volatile("barrier.cluster.arrive.aligned;" ::: "memory"); \
    asm volatile("barrier.cluster.wait.aligned;" ::: "memory"); \
} while (0)

// ---------------------------------------------------------------------------
// conversions: x -> reordered hi/lo bf16 [m=s*B+b][i]; Wx -> hi/lo
// ---------------------------------------------------------------------------
__global__ __launch_bounds__(256) void k_convert_x(const float* __restrict__ x) {
    int gid = blockIdx.x * blockDim.x + threadIdx.x;   // S*B*I/4 units
    if (gid < 16) ((unsigned*)g_flag)[gid] = 0;        // reset flags each launch
    int i4 = (gid & (I_ / 4 - 1)) * 4;
    int m  = gid >> 7;                                 // I_/4 = 128
    int s = m / B_, b = m % B_;
    float4 v = *(const float4*)(x + ((size_t)b * S_ + s) * I_ + i4);
    __nv_bfloat16 h0, l0, h1, l1, h2, l2, h3, l3;
    split2(v.x, h0, l0); split2(v.y, h1, l1);
    split2(v.z, h2, l2); split2(v.w, h3, l3);
    __nv_bfloat162 p;
    __nv_bfloat16* dh = g_xr[0] + (size_t)m * I_ + i4;
    __nv_bfloat16* dl = g_xr[1] + (size_t)m * I_ + i4;
    p.x = h0; p.y = h1; *(__nv_bfloat162*)(dh)     = p;
    p.x = h2; p.y = h3; *(__nv_bfloat162*)(dh + 2) = p;
    p.x = l0; p.y = l1; *(__nv_bfloat162*)(dl)     = p;
    p.x = l2; p.y = l3; *(__nv_bfloat162*)(dl + 2) = p;
}

__global__ __launch_bounds__(256) void k_convert_wx(const float* __restrict__ Wx) {
    int gid = blockIdx.x * blockDim.x + threadIdx.x;   // H*I/4 units
    int i = gid * 4;
    float4 v = *(const float4*)(Wx + i);
    __nv_bfloat16 h0, l0, h1, l1, h2, l2, h3, l3;
    split2(v.x, h0, l0); split2(v.y, h1, l1);
    split2(v.z, h2, l2); split2(v.w, h3, l3);
    __nv_bfloat162 p;
    p.x = h0; p.y = h1; *(__nv_bfloat162*)(g_Wxbf[0] + i)     = p;
    p.x = h2; p.y = h3; *(__nv_bfloat162*)(g_Wxbf[0] + i + 2) = p;
    p.x = l0; p.y = l1; *(__nv_bfloat162*)(g_Wxbf[1] + i)     = p;
    p.x = l2; p.y = l3; *(__nv_bfloat162*)(g_Wxbf[1] + i + 2) = p;
}

// ---------------------------------------------------------------------------
// xproj GEMM via bf16x2-split mma (unchanged)
// ---------------------------------------------------------------------------
#define XKC  64
#define XPA  72

__global__ __launch_bounds__(256) void k_xproj_mma(const float* __restrict__ bx) {
    extern __shared__ __nv_bfloat16 dsm[];
    __nv_bfloat16* sa = dsm;
    __nv_bfloat16* sb = dsm + 2 * 2 * 128 * XPA;

    const int tid = threadIdx.x;
    const int lane = tid & 31, wid = tid >> 5;
    const int n0 = blockIdx.x * 64;
    const int m0 = blockIdx.y * 128;
    const int wm = (wid & 3) * 32;
    const int wn = (wid >> 2) * 32;

    float acc[2][4][4];
#pragma unroll
    for (int a = 0; a < 2; a++)
#pragma unroll
        for (int b = 0; b < 4; b++)
#pragma unroll
            for (int c = 0; c < 4; c++) acc[a][b][c] = 0.0f;

    auto load_chunk = [&](int buf, int k0) {
#pragma unroll
        for (int sp = 0; sp < 2; sp++) {
            __nv_bfloat16* da = sa + (size_t)(buf * 2 + sp) * 128 * XPA;
            const __nv_bfloat16* ga = g_xr[sp];
#pragma unroll
            for (int q = 0; q < 4; q++) {
                int u = tid + q * 256;
                int row = u >> 3, c16 = (u & 7) * 8;
                cp_async16(da + row * XPA + c16,
                           ga + (size_t)(m0 + row) * I_ + k0 + c16);
            }
            __nv_bfloat16* db = sb + (size_t)(buf * 2 + sp) * 64 * XPA;
            const __nv_bfloat16* gb = g_Wxbf[sp];
#pragma unroll
            for (int q = 0; q < 2; q++) {
                int u = tid + q * 256;
                int row = u >> 3, c16 = (u & 7) * 8;
                cp_async16(db + row * XPA + c16,
                           gb + (size_t)(n0 + row) * I_ + k0 + c16);
            }
        }
        cp_commit();
    };

    load_chunk(0, 0);

    const int a_row  = wm + (lane & 15);
    const int a_koff = (lane >> 4) * 8;
    const int b_row  = wn + ((lane >> 4) * 8) + (lane & 7);
    const int b_koff = ((lane >> 3) & 1) * 8;

    for (int ch = 0; ch < I_ / XKC; ch++) {
        if (ch + 1 < I_ / XKC) { load_chunk((ch + 1) & 1, (ch + 1) * XKC); cp_wait<1>(); }
        else                   { cp_wait<0>(); }
        __syncthreads();
        const int buf = ch & 1;
        const __nv_bfloat16* ah_base = sa + (size_t)(buf * 2 + 0) * 128 * XPA;
        const __nv_bfloat16* al_base = sa + (size_t)(buf * 2 + 1) * 128 * XPA;
        const __nv_bfloat16* bh_base = sb + (size_t)(buf * 2 + 0) * 64 * XPA;
        const __nv_bfloat16* bl_base = sb + (size_t)(buf * 2 + 1) * 64 * XPA;
#pragma unroll
        for (int kk = 0; kk < XKC; kk += 16) {
            uint32_t ah[2][4], al[2][4];
#pragma unroll
            for (int fm = 0; fm < 2; fm++) {
                ldsm_x4(ah[fm][0], ah[fm][1], ah[fm][2], ah[fm][3],
                        sptr(ah_base + (a_row + fm * 16) * XPA + kk + a_koff));
                ldsm_x4(al[fm][0], al[fm][1], al[fm][2], al[fm][3],
                        sptr(al_base + (a_row + fm * 16) * XPA + kk + a_koff));
            }
            uint32_t bh[2][4], bl[2][4];
#pragma unroll
            for (int g = 0; g < 2; g++) {
                ldsm_x4(bh[g][0], bh[g][1], bh[g][2], bh[g][3],
                        sptr(bh_base + (b_row + g * 16) * XPA + kk + b_koff));
                ldsm_x4(bl[g][0], bl[g][1], bl[g][2], bl[g][3],
                        sptr(bl_base + (b_row + g * 16) * XPA + kk + b_koff));
            }
#pragma unroll
            for (int fm = 0; fm < 2; fm++)
#pragma unroll
                for (int fn = 0; fn < 4; fn++) {
                    int g = fn >> 1, o = (fn & 1) * 2;
                    float* c = acc[fm][fn];
                    mma_bf16(c[0], c[1], c[2], c[3],
                             ah[fm][0], ah[fm][1], ah[fm][2], ah[fm][3],
                             bh[g][o], bh[g][o + 1]);
                    mma_bf16(c[0], c[1], c[2], c[3],
                             ah[fm][0], ah[fm][1], ah[fm][2], ah[fm][3],
                             bl[g][o], bl[g][o + 1]);
                    mma_bf16(c[0], c[1], c[2], c[3],
                             al[fm][0], al[fm][1], al[fm][2], al[fm][3],
                             bh[g][o], bh[g][o + 1]);
                }
        }
        __syncthreads();
    }

    const int r = lane >> 2;
    const int cp = (lane & 3) * 2;
#pragma unroll
    for (int fn = 0; fn < 4; fn++) {
        int col = n0 + wn + fn * 8 + cp;
        float2 bias = *(const float2*)(bx + col);
#pragma unroll
        for (int fm = 0; fm < 2; fm++) {
            int mr = m0 + wm + fm * 16 + r;
            float2 v0 = make_float2(acc[fm][fn][0] + bias.x, acc[fm][fn][1] + bias.y);
            float2 v1 = make_float2(acc[fm][fn][2] + bias.x, acc[fm][fn][3] + bias.y);
            *(float2*)(g_xproj + (size_t)mr * H_ + col) = v0;
            *(float2*)(g_xproj + (size_t)(mr + 8) * H_ + col) = v1;
        }
    }
}

// ---------------------------------------------------------------------------
// Persistent recurrence kernel v5: cluster-4 multicast + fine-grained flags.
// flag[bt][f] (f = k-slice of 256 cols) arrives from its 8 producer CTAs;
// each copy-warp polls only the flag its plane needs, expects, and issues.
// ---------------------------------------------------------------------------
#define PIT  264   // halves per SMEM row (256 + 8), 528B pitch
#define REDP 33    // red row pitch (floats)
#define PLANE_BYTES (32 * PIT * 2)
#define SMEM_PLANES (8 * 32 * PIT)                     // halves
#define RED_OFF_B   (SMEM_PLANES * 2)                  // bytes
#define MBAR_OFF_B  (RED_OFF_B + 2 * 32 * REDP * 4)    // bytes (8-aligned)

__global__ __launch_bounds__(256, 1) __cluster_dims__(4, 1, 1)
void k_rnn(const float* __restrict__ Wh) {
    extern __shared__ __nv_bfloat16 dsm[];
    float* red = (float*)((char*)dsm + RED_OFF_B);     // [2][32][REDP]
    uint32_t mb0 = sptr((char*)dsm + MBAR_OFF_B);      // 4 mbarriers: [ks][sub]

    const int tid = threadIdx.x;
    const int lane = tid & 31, wid = tid >> 5;
    const int ks = wid >> 2;          // K-half group
    const int nw = wid & 3;           // n-warp (8 j-cols)
    const int gtid = tid & 127;
    const int jt = blockIdx.x & 31, bt = blockIdx.x >> 5;
    const int jb = jt * 32, bb = bt * 32;
    const uint32_t rank = cl_rank();

    // init mbarriers (arrive count 1 = the expect_tx arrival)
    if (tid == 0) {
#pragma unroll
        for (int i = 0; i < 4; i++) MBAR_INIT(mb0 + i * 8, 1);
    }
    __syncthreads();
    CLUSTER_SYNC_();   // peers' barriers live before any multicast targets them

    // --- stage this group's Wh K-half into SMEM planes (split hi/lo) ---
    {
        const int kbase = ks * 512;
#pragma unroll
        for (int sub = 0; sub < 2; sub++) {
            __nv_bfloat16* dh = dsm + ((ks * 2 + sub) * 2 + 0) * 32 * PIT;
            __nv_bfloat16* dl = dsm + ((ks * 2 + sub) * 2 + 1) * 32 * PIT;
#pragma unroll
            for (int q = 0; q < 16; q++) {
                int u = gtid + q * 128;
                int row = u >> 6;
                int c4 = (u & 63) * 4;
                float4 v = *(const float4*)(Wh + (size_t)(jb + row) * H_ + kbase + sub * 256 + c4);
                __nv_bfloat16 h0, l0, h1, l1, h2, l2, h3, l3;
                split2(v.x, h0, l0); split2(v.y, h1, l1);
                split2(v.z, h2, l2); split2(v.w, h3, l3);
                __nv_bfloat16* ph = dh + row * PIT + c4;
                __nv_bfloat16* pl = dl + row * PIT + c4;
                ph[0] = h0; ph[1] = h1; ph[2] = h2; ph[3] = h3;
                pl[0] = l0; pl[1] = l1; pl[2] = l2; pl[3] = l3;
            }
        }
    }
    __syncthreads();

    // --- register-resident Wh fragments (n8 x K512 per warp) ---
    const int b_row  = nw * 8 + (lane & 7);
    const int b_koff = (lane >> 3) * 8;
    uint32_t bfh[16][4], bfl[16][4];
#pragma unroll
    for (int g = 0; g < 16; g++) {
        int sub = g >> 3, col = (g & 7) * 32 + b_koff;
        const __nv_bfloat16* ph = dsm + ((ks * 2 + sub) * 2 + 0) * 32 * PIT;
        const __nv_bfloat16* pl = dsm + ((ks * 2 + sub) * 2 + 1) * 32 * PIT;
        ldsm_x4(bfh[g][0], bfh[g][1], bfh[g][2], bfh[g][3], sptr(ph + b_row * PIT + col));
        ldsm_x4(bfl[g][0], bfl[g][1], bfl[g][2], bfl[g][3], sptr(pl + b_row * PIT + col));
    }
    __syncthreads();

    // epilogue mapping (all 256 threads, 4 outputs each)
    const int erow = tid >> 3;
    const int ecol = (tid & 7) * 4;

    // --- t = 0: h(1) = tanh(xproj[0]) ---
    {
        float4 v = *(const float4*)(g_xproj + (size_t)(bb + erow) * H_ + jb + ecol);
        float t0 = tanhf(v.x), t1 = tanhf(v.y), t2 = tanhf(v.z), t3 = tanhf(v.w);
        __nv_bfloat16 h0, l0, h1, l1, h2, l2, h3, l3;
        split2(t0, h0, l0); split2(t1, h1, l1);
        split2(t2, h2, l2); split2(t3, h3, l3);
        __nv_bfloat162 p01, p23;
        uint2 u;
        p01.x = h0; p01.y = h1; p23.x = h2; p23.y = h3;
        u.x = *(uint32_t*)&p01; u.y = *(uint32_t*)&p23;
        *(uint2*)(g_hbf[1][0] + (size_t)(bb + erow) * H_ + jb + ecol) = u;
        p01.x = l0; p01.y = l1; p23.x = l2; p23.y = l3;
        u.x = *(uint32_t*)&p01; u.y = *(uint32_t*)&p23;
        *(uint2*)(g_hbf[1][1] + (size_t)(bb + erow) * H_ + jb + ecol) = u;
    }
    __syncthreads();
    if (tid == 0) bar_arrive(&g_flag[bt][jt >> 3]);

    const int a_row  = lane & 15;
    const int a_koff = (lane >> 4) * 8;
    const int srow = lane >> 2;
    const int scol = nw * 8 + (lane & 3) * 2;

    // copy-issue role: warp wid handles plane wid, rows [rank*8, rank*8+8)
    const int ip   = wid;                // plane 0..7
    const int isp  = ip & 1;             // split (hi/lo)
    const int isub = (ip >> 1) & 1;      // sub-chunk
    const int iks  = ip >> 2;            // K-half
    const int ifl  = ip >> 1;            // flag / mbar index (= iks*2+isub)
    const uint32_t idst0 = sptr((char*)dsm + (size_t)ip * PLANE_BYTES) + rank * 8 * PIT * 2;
    const uint32_t imbar = mb0 + ifl * 8;
    unsigned* iflag = &g_flag[bt][ifl];

    for (int t = 1; t < S_; t++) {
        // independent prefetch fills the wait shadow
        const float* xp = g_xproj + (size_t)t * B_ * H_;
        float4 xv = __ldg((const float4*)(xp + (size_t)(bb + erow) * H_ + jb + ecol));

        // per-warp: poll only the producers of this plane's k-slice, then ship it
        if (lane == 0) {
            bar_wait(iflag, 8u * (unsigned)t);
            if (isp == 0) MBAR_EXPECT(imbar, 32768u);
            const __nv_bfloat16* src = g_hbf[t & 1][isp];
            const size_t base = (size_t)(bb + rank * 8) * H_ + iks * 512 + isub * 256;
#pragma unroll
            for (int rrow = 0; rrow < 8; rrow++) {
                BULK_MC(idst0 + rrow * PIT * 2,
                        src + base + (size_t)rrow * H_,
                        512u, imbar, 0xFu);
            }
        }

        float c1[2][4] = {0}, c2[2][4] = {0}, c3[2][4] = {0};

        auto do_group = [&](int g) {
            const int sub = g >> 3;
            const int cb = (g & 7) * 32;
            const __nv_bfloat16* ph = dsm + ((ks * 2 + sub) * 2 + 0) * 32 * PIT;
            const __nv_bfloat16* pl = dsm + ((ks * 2 + sub) * 2 + 1) * 32 * PIT;
            uint32_t ah[2][2][4], al[2][2][4];
#pragma unroll
            for (int fm = 0; fm < 2; fm++)
#pragma unroll
                for (int kh = 0; kh < 2; kh++) {
                    ldsm_x4(ah[fm][kh][0], ah[fm][kh][1], ah[fm][kh][2], ah[fm][kh][3],
                            sptr(ph + (a_row + fm * 16) * PIT + cb + kh * 16 + a_koff));
                    ldsm_x4(al[fm][kh][0], al[fm][kh][1], al[fm][kh][2], al[fm][kh][3],
                            sptr(pl + (a_row + fm * 16) * PIT + cb + kh * 16 + a_koff));
                }
#pragma unroll
            for (int fm = 0; fm < 2; fm++)
#pragma unroll
                for (int kh = 0; kh < 2; kh++) {
                    mma_bf16(c1[fm][0], c1[fm][1], c1[fm][2], c1[fm][3],
                             ah[fm][kh][0], ah[fm][kh][1], ah[fm][kh][2], ah[fm][kh][3],
                             bfh[g][kh * 2], bfh[g][kh * 2 + 1]);
                    mma_bf16(c2[fm][0], c2[fm][1], c2[fm][2], c2[fm][3],
                             ah[fm][kh][0], ah[fm][kh][1], ah[fm][kh][2], ah[fm][kh][3],
                             bfl[g][kh * 2], bfl[g][kh * 2 + 1]);
                    mma_bf16(c3[fm][0], c3[fm][1], c3[fm][2], c3[fm][3],
                             al[fm][kh][0], al[fm][kh][1], al[fm][kh][2], al[fm][kh][3],
                             bfh[g][kh * 2], bfh[g][kh * 2 + 1]);
                }
        };

        const uint32_t ph_par = (unsigned)(t - 1) & 1u;
        MBAR_WAIT(mb0 + (ks * 2 + 0) * 8, ph_par);
#pragma unroll
        for (int g = 0; g < 8; g++) do_group(g);
        MBAR_WAIT(mb0 + (ks * 2 + 1) * 8, ph_par);
#pragma unroll
        for (int g = 8; g < 16; g++) do_group(g);

        // scatter partial sums to SMEM red[ks]
        float* rb = red + ks * 32 * REDP;
#pragma unroll
        for (int fm = 0; fm < 2; fm++) {
            float s0 = c1[fm][0] + c2[fm][0] + c3[fm][0];
            float s1 = c1[fm][1] + c2[fm][1] + c3[fm][1];
            float s2 = c1[fm][2] + c2[fm][2] + c3[fm][2];
            float s3 = c1[fm][3] + c2[fm][3] + c3[fm][3];
            rb[(fm * 16 + srow) * REDP + scol]     = s0;
            rb[(fm * 16 + srow) * REDP + scol + 1] = s1;
            rb[(fm * 16 + 8 + srow) * REDP + scol]     = s2;
            rb[(fm * 16 + 8 + srow) * REDP + scol + 1] = s3;
        }
        __syncthreads();

        // cooperative epilogue: 4 outputs per thread
        {
            const float* r0 = red + erow * REDP + ecol;
            const float* r1 = red + 32 * REDP + erow * REDP + ecol;
            float z0 = tanhf(r0[0] + r1[0] + xv.x);
            float z1 = tanhf(r0[1] + r1[1] + xv.y);
            float z2 = tanhf(r0[2] + r1[2] + xv.z);
            float z3 = tanhf(r0[3] + r1[3] + xv.w);

            if (t < S_ - 1) {
                __nv_bfloat16 h0, l0, h1, l1, h2, l2, h3, l3;
                split2(z0, h0, l0); split2(z1, h1, l1);
                split2(z2, h2, l2); split2(z3, h3, l3);
                __nv_bfloat162 p01, p23;
                uint2 u;
                p01.x = h0; p01.y = h1; p23.x = h2; p23.y = h3;
                u.x = *(uint32_t*)&p01; u.y = *(uint32_t*)&p23;
                *(uint2*)(g_hbf[(t + 1) & 1][0] + (size_t)(bb + erow) * H_ + jb + ecol) = u;
                p01.x = l0; p01.y = l1; p23.x = l2; p23.y = l3;
                u.x = *(uint32_t*)&p01; u.y = *(uint32_t*)&p23;
                *(uint2*)(g_hbf[(t + 1) & 1][1] + (size_t)(bb + erow) * H_ + jb + ecol) = u;
            } else {
                *(float4*)(g_hf + (size_t)(bb + erow) * H_ + jb + ecol) =
                    make_float4(z0, z1, z2, z3);
            }
        }
        __syncthreads();
        if (tid == 0 && t < S_ - 1) bar_arrive(&g_flag[bt][jt >> 3]);
    }
    CLUSTER_SYNC_();   // no CTA exits while peers' multicasts may target it
}

// ---------------------------------------------------------------------------
// Final projection (fp32 SIMT, tiny)
// ---------------------------------------------------------------------------
#define KC   64
#define SROW (KC + 4)

__global__ __launch_bounds__(256) void k_final(const float* __restrict__ Wp,
                                               const float* __restrict__ bp,
                                               float* __restrict__ out) {
    __shared__ float hs[2][32][SROW];
    __shared__ float ws[2][32][SROW];
    const int tid = threadIdx.x;
    const int jb = blockIdx.x * 32;
    const int bb = blockIdx.y * 32;
    const float* __restrict__ hin = g_hf;

    const int r0 = tid >> 4;
    const int c0 = (tid & 15) << 2;

    float4 acc00 = {0,0,0,0}, acc01 = {0,0,0,0}, acc10 = {0,0,0,0}, acc11 = {0,0,0,0};
    const int b0 = (tid >> 4) << 1;
    const int j0 = tid & 15;

    {
#pragma unroll
        for (int q = 0; q < 2; q++) {
            int row = r0 + q * 16;
            cp_async16(&hs[0][row][c0], hin + (size_t)(bb + row) * H_ + c0);
            cp_async16(&ws[0][row][c0], Wp  + (size_t)(jb + row) * H_ + c0);
        }
        cp_commit();
    }

    for (int c = 0; c < H_ / KC; c++) {
        if (c + 1 < H_ / KC) {
            int k0 = (c + 1) * KC;
            int nb = (c + 1) & 1;
#pragma unroll
            for (int q = 0; q < 2; q++) {
                int row = r0 + q * 16;
                cp_async16(&hs[nb][row][c0], hin + (size_t)(bb + row) * H_ + k0 + c0);
                cp_async16(&ws[nb][row][c0], Wp  + (size_t)(jb + row) * H_ + k0 + c0);
            }
            cp_commit();
            cp_wait<1>();
        } else {
            cp_wait<0>();
        }
        __syncthreads();
        const int buf = c & 1;
#pragma unroll
        for (int k4 = 0; k4 < KC; k4 += 4) {
            float4 a0 = *(const float4*)&hs[buf][b0    ][k4];
            float4 a1 = *(const float4*)&hs[buf][b0 + 1][k4];
            float4 w0 = *(const float4*)&ws[buf][j0     ][k4];
            float4 w1 = *(const float4*)&ws[buf][j0 + 16][k4];
            fma4(acc00, a0, w0); fma4(acc01, a0, w1);
            fma4(acc10, a1, w0); fma4(acc11, a1, w1);
        }
        __syncthreads();
    }

    {
        int bg = bb + b0, jg = jb + j0;
        float z;
        z = (acc00.x + acc00.y) + (acc00.z + acc00.w) + bp[jg];
        out[(size_t)bg * O_ + jg] = z;
        z = (acc01.x + acc01.y) + (acc01.z + acc01.w) + bp[jg + 16];
        out[(size_t)bg * O_ + jg + 16] = z;
        z = (acc10.x + acc10.y) + (acc10.z + acc10.w) + bp[jg];
        out[(size_t)(bg + 1) * O_ + jg] = z;
        z = (acc11.x + acc11.y) + (acc11.z + acc11.w) + bp[jg + 16];
        out[(size_t)(bg + 1) * O_ + jg + 16] = z;
    }
}

// ---------------------------------------------------------------------------
// launch
// ---------------------------------------------------------------------------
extern "C" void kernel_launch(void* const* d_in, const int* in_sizes, int n_in,
                              void* d_out, int out_size) {
    const float* x  = (const float*)d_in[0];
    const float* Wx = (const float*)d_in[1];
    const float* bx = (const float*)d_in[2];
    const float* Wh = (const float*)d_in[3];
    const float* Wp = (const float*)d_in[4];
    const float* bp = (const float*)d_in[5];
    float* out = (float*)d_out;

    const int XSMEM = (2 * 2 * 128 * XPA + 2 * 2 * 64 * XPA) * (int)sizeof(__nv_bfloat16);
    const int RSMEM = MBAR_OFF_B + 4 * 8;
    cudaFuncSetAttribute(k_xproj_mma, cudaFuncAttributeMaxDynamicSharedMemorySize, XSMEM);
    cudaFuncSetAttribute(k_rnn, cudaFuncAttributeMaxDynamicSharedMemorySize, RSMEM);

    k_convert_x<<<(S_ * B_ * I_ / 4) / 256, 256>>>(x);
    k_convert_wx<<<(H_ * I_ / 4) / 256, 256>>>(Wx);
    k_xproj_mma<<<dim3(H_ / 64, (B_ * S_) / 128), 256, XSMEM>>>(bx);
    k_rnn<<<NCTA, 256, RSMEM>>>(Wh);
    k_final<<<dim3(O_ / 32, B_ / 32), 256>>>(Wp, bp, out);
}